// round 7
// baseline (speedup 1.0000x reference)
#include <cuda_runtime.h>
#include <math.h>
#include <stdint.h>

// Problem dims
#define BB 32
#define TT 256
#define CC 384
#define LL 6
#define NH 6
#define HD 64
#define VV 32000
#define MM (BB*TT)      // 8192
#define FF (4*CC)       // 1536

// tf32 weight scratch layout (element offsets)
#define OFF_WQ 0
#define OFF_WK 884736
#define OFF_WV 1769472
#define OFF_WO 2654208
#define OFF_W1 3538944
#define OFF_W2 7077888
#define OFF_LM 10616832
#define WT_TOTAL 22904832

// Scratch (device globals; no allocations allowed)
__device__ float    g_x[MM*CC];          // residual stream (f32)
__device__ uint32_t g_h[MM*CC];          // LN output (tf32)
__device__ uint32_t g_q[MM*CC];
__device__ uint32_t g_k[MM*CC];
__device__ uint32_t g_v[MM*CC];
__device__ uint32_t g_att[MM*CC];
__device__ uint32_t g_u[MM*FF];
__device__ uint32_t g_wt[WT_TOTAL];      // tf32 weights

// ---------------------------------------------------------------------------
// Helpers
// ---------------------------------------------------------------------------
__device__ __forceinline__ uint32_t f2tf(float f) {
    uint32_t u;
    asm("cvt.rna.tf32.f32 %0, %1;" : "=r"(u) : "f"(f));
    return u;
}

__device__ __forceinline__ void mma_tf32(float* c, const uint32_t* a, const uint32_t* b) {
    asm volatile(
        "mma.sync.aligned.m16n8k8.row.col.f32.tf32.tf32.f32 "
        "{%0,%1,%2,%3}, {%4,%5,%6,%7}, {%8,%9}, {%0,%1,%2,%3};"
        : "+f"(c[0]), "+f"(c[1]), "+f"(c[2]), "+f"(c[3])
        : "r"(a[0]), "r"(a[1]), "r"(a[2]), "r"(a[3]),
          "r"(b[0]), "r"(b[1]));
}

__device__ __forceinline__ void cp_async16(void* sptr, const void* gptr) {
    uint32_t sa = (uint32_t)__cvta_generic_to_shared(sptr);
    asm volatile("cp.async.cg.shared.global [%0], [%1], 16;\n" :: "r"(sa), "l"(gptr));
}
#define CP_COMMIT() asm volatile("cp.async.commit_group;\n" ::: "memory")
#define CP_WAIT0()  asm volatile("cp.async.wait_group 0;\n" ::: "memory")
#define CP_WAIT1()  asm volatile("cp.async.wait_group 1;\n" ::: "memory")

// ---------------------------------------------------------------------------
// f32 -> tf32 conversion (vectorized by 4)
// ---------------------------------------------------------------------------
__global__ void cvt_kernel(const float* __restrict__ src, uint32_t* __restrict__ dst, int n4)
{
    int i = blockIdx.x * blockDim.x + threadIdx.x;
    if (i >= n4) return;
    float4 v = *(const float4*)(src + (size_t)i*4);
    uint4 u;
    u.x = f2tf(v.x); u.y = f2tf(v.y); u.z = f2tf(v.z); u.w = f2tf(v.w);
    *(uint4*)(dst + (size_t)i*4) = u;
}

// ---------------------------------------------------------------------------
// Embedding (f32 residual stream)
// ---------------------------------------------------------------------------
__global__ void embed_kernel(const int* __restrict__ idx,
                             const float* __restrict__ tok,
                             const float* __restrict__ pos,
                             float* __restrict__ X)
{
    int i = blockIdx.x * blockDim.x + threadIdx.x;
    if (i >= MM * (CC/4)) return;
    int row = i / (CC/4);
    int c4  = i % (CC/4);
    int t   = idx[row];
    int p   = row & (TT-1);
    float4 a = *(const float4*)(tok + (size_t)t*CC + c4*4);
    float4 e = *(const float4*)(pos + (size_t)p*CC + c4*4);
    a.x += e.x; a.y += e.y; a.z += e.z; a.w += e.w;
    *(float4*)(X + (size_t)row*CC + c4*4) = a;
}

// ---------------------------------------------------------------------------
// LayerNorm: one warp per row; output tf32
// ---------------------------------------------------------------------------
__global__ void ln_kernel(const float* __restrict__ X,
                          const float* __restrict__ g,
                          const float* __restrict__ b,
                          uint32_t* __restrict__ Y)
{
    int row  = blockIdx.x * 8 + (threadIdx.x >> 5);
    int lane = threadIdx.x & 31;
    if (row >= MM) return;
    const float* x = X + (size_t)row*CC;
    float v[12];
    float s = 0.f, ss = 0.f;
#pragma unroll
    for (int i = 0; i < 12; i++) {
        v[i] = x[lane + i*32];
        s  += v[i];
        ss += v[i]*v[i];
    }
#pragma unroll
    for (int o = 16; o; o >>= 1) {
        s  += __shfl_xor_sync(0xFFFFFFFFu, s,  o);
        ss += __shfl_xor_sync(0xFFFFFFFFu, ss, o);
    }
    float mean = s  * (1.0f/CC);
    float var  = ss * (1.0f/CC) - mean*mean;
    float inv  = rsqrtf(var + 1e-5f);
    uint32_t* y = Y + (size_t)row*CC;
#pragma unroll
    for (int i = 0; i < 12; i++) {
        int c = lane + i*32;
        y[c] = f2tf((v[i]-mean)*inv*g[c] + b[c]);
    }
}

// ---------------------------------------------------------------------------
// TF32 GEMM (layer): 128x128 tile, BK=32, 128 threads, warp tile 64x64.
// 3-stage cp.async pipeline, wait_group 1.
// ---------------------------------------------------------------------------
struct GemmSmem {
    uint32_t As[3][128][36];
    uint32_t Bs[3][32][136];
};
#define SMEM_GEMM ((int)sizeof(GemmSmem))   // 107520 bytes

template<bool RELU, bool RES, bool OUTTF>
__device__ __forceinline__
void gemm_core(GemmSmem* sm,
               const uint32_t* __restrict__ A, const uint32_t* __restrict__ B,
               const float* __restrict__ bias, const float* __restrict__ res,
               void* __restrict__ Cv, int M, int N, int K, int bm, int bn)
{
    const int tid  = threadIdx.x;
    const int lane = tid & 31;
    const int wid  = tid >> 5;
    const int wm = (wid & 1) * 64;
    const int wn = (wid >> 1) * 64;
    const int grp = lane >> 2;
    const int tg  = lane & 3;

    float acc[4][8][4];
#pragma unroll
    for (int mt = 0; mt < 4; mt++)
#pragma unroll
        for (int nt = 0; nt < 8; nt++)
#pragma unroll
            for (int e = 0; e < 4; e++) acc[mt][nt][e] = 0.f;

    auto issue = [&](int s, int k0) {
#pragma unroll
        for (int p = 0; p < 8; p++) {
            int i  = tid + p*128;
            int r  = i >> 3;
            int c4 = (i & 7) * 4;
            cp_async16(&sm->As[s][r][c4], A + (size_t)(bm + r)*K + k0 + c4);
        }
#pragma unroll
        for (int p = 0; p < 8; p++) {
            int i  = tid + p*128;
            int r  = i >> 5;
            int c4 = (i & 31) * 4;
            cp_async16(&sm->Bs[s][r][c4], B + (size_t)(k0 + r)*N + bn + c4);
        }
        CP_COMMIT();
    };

    const int nIter = K >> 5;
    issue(0, 0);
    issue(1, 32);

    int cur = 0;
    for (int it = 0; it < nIter; it++) {
        CP_WAIT1();
        __syncthreads();
        if (it + 2 < nIter) {
            int nxt = cur + 2; if (nxt >= 3) nxt -= 3;
            issue(nxt, (it + 2) << 5);
        }

#pragma unroll
        for (int kk = 0; kk < 32; kk += 8) {
            uint32_t af[4][4], bf[8][2];
#pragma unroll
            for (int mt = 0; mt < 4; mt++) {
                int r = wm + mt*16 + grp;
                af[mt][0] = sm->As[cur][r    ][kk + tg    ];
                af[mt][1] = sm->As[cur][r + 8][kk + tg    ];
                af[mt][2] = sm->As[cur][r    ][kk + tg + 4];
                af[mt][3] = sm->As[cur][r + 8][kk + tg + 4];
            }
#pragma unroll
            for (int nt = 0; nt < 8; nt++) {
                int c = wn + nt*8 + grp;
                bf[nt][0] = sm->Bs[cur][kk + tg    ][c];
                bf[nt][1] = sm->Bs[cur][kk + tg + 4][c];
            }
#pragma unroll
            for (int mt = 0; mt < 4; mt++)
#pragma unroll
                for (int nt = 0; nt < 8; nt++)
                    mma_tf32(acc[mt][nt], af[mt], bf[nt]);
        }
        cur++; if (cur >= 3) cur -= 3;
    }

    // Epilogue
#pragma unroll
    for (int mt = 0; mt < 4; mt++) {
        int r0 = bm + wm + mt*16 + grp;
        int r1 = r0 + 8;
#pragma unroll
        for (int nt = 0; nt < 8; nt++) {
            int c = bn + wn + nt*8 + tg*2;
            float o0x = acc[mt][nt][0], o0y = acc[mt][nt][1];
            float o1x = acc[mt][nt][2], o1y = acc[mt][nt][3];
            if (bias) {
                float bv0 = bias[c], bv1 = bias[c+1];
                o0x += bv0; o0y += bv1; o1x += bv0; o1y += bv1;
            }
            if (RES) {
                float2 ra = *(const float2*)(res + (size_t)r0*N + c);
                float2 rb = *(const float2*)(res + (size_t)r1*N + c);
                o0x += ra.x; o0y += ra.y; o1x += rb.x; o1y += rb.y;
            }
            if (RELU) {
                o0x = fmaxf(o0x, 0.f); o0y = fmaxf(o0y, 0.f);
                o1x = fmaxf(o1x, 0.f); o1y = fmaxf(o1y, 0.f);
            }
            if (OUTTF) {
                uint32_t* C = (uint32_t*)Cv;
                uint2 w0 = {f2tf(o0x), f2tf(o0y)};
                uint2 w1 = {f2tf(o1x), f2tf(o1y)};
                *(uint2*)(C + (size_t)r0*N + c) = w0;
                *(uint2*)(C + (size_t)r1*N + c) = w1;
            } else {
                float* C = (float*)Cv;
                float2 w0 = {o0x, o0y};
                float2 w1 = {o1x, o1y};
                *(float2*)(C + (size_t)r0*N + c) = w0;
                *(float2*)(C + (size_t)r1*N + c) = w1;
            }
        }
    }
}

template<bool RELU, bool RES, bool OUTTF>
__global__ __launch_bounds__(128)
void tgemm(const uint32_t* __restrict__ A, const uint32_t* __restrict__ B,
           const float* __restrict__ bias, const float* __restrict__ res,
           void* __restrict__ C, int M, int N, int K)
{
    extern __shared__ GemmSmem smg[];
    gemm_core<RELU, RES, OUTTF>(smg, A, B, bias, res, C, M, N, K,
                                blockIdx.y * 128, blockIdx.x * 128);
}

// Fused QKV: grid.x = 9 (3 matrices x 3 col-tiles), grid.y = 64. tf32 out.
__global__ __launch_bounds__(128)
void qkv_gemm(const uint32_t* __restrict__ A,
              const uint32_t* __restrict__ Wq, const uint32_t* __restrict__ Wk,
              const uint32_t* __restrict__ Wv,
              uint32_t* __restrict__ Q, uint32_t* __restrict__ Ko, uint32_t* __restrict__ V)
{
    extern __shared__ GemmSmem smg[];
    int sel = blockIdx.x / 3;
    int bn  = (blockIdx.x % 3) * 128;
    const uint32_t* B = (sel == 0) ? Wq : (sel == 1) ? Wk : Wv;
    uint32_t*       C = (sel == 0) ? Q  : (sel == 1) ? Ko : V;
    gemm_core<false, false, true>(smg, A, B, nullptr, nullptr, C,
                                  MM, CC, CC, blockIdx.y * 128, bn);
}

// ---------------------------------------------------------------------------
// Big-M GEMM for LM head: 256x128 tile, BK=32, 256 threads (8 warps, 4x2 of
// 64x64), 2-stage cp.async. Halves A re-reads through L2 vs 128x128.
// ---------------------------------------------------------------------------
struct GemmSmemBig {
    uint32_t As[2][256][36];
    uint32_t Bs[2][32][136];
};
#define SMEM_GEMM_BIG ((int)sizeof(GemmSmemBig))   // 108544 bytes

__global__ __launch_bounds__(256)
void tgemm_big(const uint32_t* __restrict__ A, const uint32_t* __restrict__ B,
               const float* __restrict__ bias, float* __restrict__ C,
               int M, int N, int K)
{
    extern __shared__ GemmSmemBig smb[];
    GemmSmemBig* sm = smb;

    const int bm = blockIdx.y * 256;
    const int bn = blockIdx.x * 128;
    const int tid  = threadIdx.x;
    const int lane = tid & 31;
    const int wid  = tid >> 5;
    const int wm = (wid & 3) * 64;
    const int wn = (wid >> 2) * 64;
    const int grp = lane >> 2;
    const int tg  = lane & 3;

    float acc[4][8][4];
#pragma unroll
    for (int mt = 0; mt < 4; mt++)
#pragma unroll
        for (int nt = 0; nt < 8; nt++)
#pragma unroll
            for (int e = 0; e < 4; e++) acc[mt][nt][e] = 0.f;

    auto issue = [&](int s, int k0) {
#pragma unroll
        for (int p = 0; p < 8; p++) {
            int i  = tid + p*256;
            int r  = i >> 3;
            int c4 = (i & 7) * 4;
            cp_async16(&sm->As[s][r][c4], A + (size_t)(bm + r)*K + k0 + c4);
        }
#pragma unroll
        for (int p = 0; p < 4; p++) {
            int i  = tid + p*256;
            int r  = i >> 5;
            int c4 = (i & 31) * 4;
            cp_async16(&sm->Bs[s][r][c4], B + (size_t)(k0 + r)*N + bn + c4);
        }
        CP_COMMIT();
    };

    const int nIter = K >> 5;
    issue(0, 0);

    for (int it = 0; it < nIter; it++) {
        const int cur = it & 1;
        CP_WAIT0();
        __syncthreads();
        if (it + 1 < nIter) issue(cur ^ 1, (it + 1) << 5);

#pragma unroll
        for (int kk = 0; kk < 32; kk += 8) {
            uint32_t af[4][4], bf[8][2];
#pragma unroll
            for (int mt = 0; mt < 4; mt++) {
                int r = wm + mt*16 + grp;
                af[mt][0] = sm->As[cur][r    ][kk + tg    ];
                af[mt][1] = sm->As[cur][r + 8][kk + tg    ];
                af[mt][2] = sm->As[cur][r    ][kk + tg + 4];
                af[mt][3] = sm->As[cur][r + 8][kk + tg + 4];
            }
#pragma unroll
            for (int nt = 0; nt < 8; nt++) {
                int c = wn + nt*8 + grp;
                bf[nt][0] = sm->Bs[cur][kk + tg    ][c];
                bf[nt][1] = sm->Bs[cur][kk + tg + 4][c];
            }
#pragma unroll
            for (int mt = 0; mt < 4; mt++)
#pragma unroll
                for (int nt = 0; nt < 8; nt++)
                    mma_tf32(acc[mt][nt], af[mt], bf[nt]);
        }
    }

#pragma unroll
    for (int mt = 0; mt < 4; mt++) {
        int r0 = bm + wm + mt*16 + grp;
        int r1 = r0 + 8;
#pragma unroll
        for (int nt = 0; nt < 8; nt++) {
            int c = bn + wn + nt*8 + tg*2;
            float bv0 = bias[c], bv1 = bias[c+1];
            float2 w0 = {acc[mt][nt][0] + bv0, acc[mt][nt][1] + bv1};
            float2 w1 = {acc[mt][nt][2] + bv0, acc[mt][nt][3] + bv1};
            *(float2*)(C + (size_t)r0*N + c) = w0;
            *(float2*)(C + (size_t)r1*N + c) = w1;
        }
    }
}

// ---------------------------------------------------------------------------
// Tensor-core flash attention; q/k/v tf32, att output tf32.
// ---------------------------------------------------------------------------
#define AKS 68
#define AVS 72
#define APS 36
#define ATT_SMEM ((TT*AKS + TT*AVS + 8*32*APS) * (int)sizeof(uint32_t))

__global__ __launch_bounds__(256, 1)
void attn_mma(const uint32_t* __restrict__ Q, const uint32_t* __restrict__ K,
              const uint32_t* __restrict__ V, uint32_t* __restrict__ O)
{
    extern __shared__ uint32_t sm[];
    uint32_t* Ks = sm;
    uint32_t* Vs = sm + TT*AKS;
    uint32_t* Pb = sm + TT*AKS + TT*AVS;

    const int bh = blockIdx.x;
    const int b  = bh / NH;
    const int h  = bh % NH;
    const float scale = 0.05103103630798288f;  // 1/sqrt(384)

    const int tid = threadIdx.x;
    const uint32_t* kbase = K + (size_t)b*TT*CC + h*HD;
    const uint32_t* vbase = V + (size_t)b*TT*CC + h*HD;

    for (int i = tid; i < TT*16; i += 256) {
        int t  = i >> 4;
        int d4 = (i & 15) * 4;
        *(uint4*)&Ks[t*AKS + d4] = *(const uint4*)(kbase + (size_t)t*CC + d4);
        *(uint4*)&Vs[t*AVS + d4] = *(const uint4*)(vbase + (size_t)t*CC + d4);
    }
    __syncthreads();

    const int lane = tid & 31;
    const int w    = tid >> 5;
    const int grp  = lane >> 2;
    const int tg   = lane & 3;
    const int q0   = w * 32;

    const uint32_t* qbase = Q + (size_t)b*TT*CC + h*HD;
    uint32_t qa[2][8][4];
#pragma unroll
    for (int mt = 0; mt < 2; mt++) {
        int ra = q0 + mt*16 + grp;
        int rb = ra + 8;
#pragma unroll
        for (int ks = 0; ks < 8; ks++) {
            int d = ks*8 + tg;
            qa[mt][ks][0] = qbase[(size_t)ra*CC + d    ];
            qa[mt][ks][1] = qbase[(size_t)rb*CC + d    ];
            qa[mt][ks][2] = qbase[(size_t)ra*CC + d + 4];
            qa[mt][ks][3] = qbase[(size_t)rb*CC + d + 4];
        }
    }

    float o[2][8][4];
#pragma unroll
    for (int mt = 0; mt < 2; mt++)
#pragma unroll
        for (int nt = 0; nt < 8; nt++)
#pragma unroll
            for (int e = 0; e < 4; e++) o[mt][nt][e] = 0.f;

    float mrow[2][2] = {{-1e30f,-1e30f},{-1e30f,-1e30f}};
    float lrow[2][2] = {{0.f,0.f},{0.f,0.f}};

    uint32_t* myP = Pb + w * 32 * APS;

    for (int j = 0; j <= w; j++) {
        const int kbeg = j * 32;
        float s[2][4][4];
#pragma unroll
        for (int mt = 0; mt < 2; mt++)
#pragma unroll
            for (int nt = 0; nt < 4; nt++)
#pragma unroll
                for (int e = 0; e < 4; e++) s[mt][nt][e] = 0.f;

#pragma unroll
        for (int ks = 0; ks < 8; ks++) {
            uint32_t bf[4][2];
#pragma unroll
            for (int nt = 0; nt < 4; nt++) {
                int key = kbeg + nt*8 + grp;
                int d   = ks*8 + tg;
                bf[nt][0] = Ks[key*AKS + d    ];
                bf[nt][1] = Ks[key*AKS + d + 4];
            }
#pragma unroll
            for (int mt = 0; mt < 2; mt++)
#pragma unroll
                for (int nt = 0; nt < 4; nt++)
                    mma_tf32(s[mt][nt], qa[mt][ks], bf[nt]);
        }

#pragma unroll
        for (int mt = 0; mt < 2; mt++) {
            int ra = q0 + mt*16 + grp;
            int rb = ra + 8;
            float rmax0 = -1e30f, rmax1 = -1e30f;
#pragma unroll
            for (int nt = 0; nt < 4; nt++) {
                int c0 = kbeg + nt*8 + 2*tg;
#pragma unroll
                for (int e = 0; e < 4; e++) {
                    float vv = s[mt][nt][e] * scale;
                    int col = c0 + (e & 1);
                    int row = (e < 2) ? ra : rb;
                    if (j == w && col > row) vv = -1e30f;
                    s[mt][nt][e] = vv;
                }
                rmax0 = fmaxf(rmax0, fmaxf(s[mt][nt][0], s[mt][nt][1]));
                rmax1 = fmaxf(rmax1, fmaxf(s[mt][nt][2], s[mt][nt][3]));
            }
            rmax0 = fmaxf(rmax0, __shfl_xor_sync(0xFFFFFFFFu, rmax0, 1));
            rmax0 = fmaxf(rmax0, __shfl_xor_sync(0xFFFFFFFFu, rmax0, 2));
            rmax1 = fmaxf(rmax1, __shfl_xor_sync(0xFFFFFFFFu, rmax1, 1));
            rmax1 = fmaxf(rmax1, __shfl_xor_sync(0xFFFFFFFFu, rmax1, 2));

            float mn0 = fmaxf(mrow[mt][0], rmax0);
            float mn1 = fmaxf(mrow[mt][1], rmax1);
            float cr0 = __expf(mrow[mt][0] - mn0);
            float cr1 = __expf(mrow[mt][1] - mn1);
            mrow[mt][0] = mn0; mrow[mt][1] = mn1;

            float rs0 = 0.f, rs1 = 0.f;
#pragma unroll
            for (int nt = 0; nt < 4; nt++) {
                float p0 = __expf(s[mt][nt][0] - mn0);
                float p1 = __expf(s[mt][nt][1] - mn0);
                float p2 = __expf(s[mt][nt][2] - mn1);
                float p3 = __expf(s[mt][nt][3] - mn1);
                rs0 += p0 + p1; rs1 += p2 + p3;
                int cb = nt*8 + 2*tg;
                myP[(mt*16 + grp    )*APS + cb    ] = f2tf(p0);
                myP[(mt*16 + grp    )*APS + cb + 1] = f2tf(p1);
                myP[(mt*16 + grp + 8)*APS + cb    ] = f2tf(p2);
                myP[(mt*16 + grp + 8)*APS + cb + 1] = f2tf(p3);
            }
            rs0 += __shfl_xor_sync(0xFFFFFFFFu, rs0, 1);
            rs0 += __shfl_xor_sync(0xFFFFFFFFu, rs0, 2);
            rs1 += __shfl_xor_sync(0xFFFFFFFFu, rs1, 1);
            rs1 += __shfl_xor_sync(0xFFFFFFFFu, rs1, 2);
            lrow[mt][0] = lrow[mt][0]*cr0 + rs0;
            lrow[mt][1] = lrow[mt][1]*cr1 + rs1;
#pragma unroll
            for (int nt = 0; nt < 8; nt++) {
                o[mt][nt][0] *= cr0; o[mt][nt][1] *= cr0;
                o[mt][nt][2] *= cr1; o[mt][nt][3] *= cr1;
            }
        }
        __syncwarp();

#pragma unroll
        for (int ks2 = 0; ks2 < 4; ks2++) {
            uint32_t vb[8][2];
#pragma unroll
            for (int nt = 0; nt < 8; nt++) {
                int key = kbeg + ks2*8 + tg;
                int d   = nt*8 + grp;
                vb[nt][0] = Vs[ key     *AVS + d];
                vb[nt][1] = Vs[(key + 4)*AVS + d];
            }
#pragma unroll
            for (int mt = 0; mt < 2; mt++) {
                uint32_t pa[4];
                pa[0] = myP[(mt*16 + grp    )*APS + ks2*8 + tg    ];
                pa[1] = myP[(mt*16 + grp + 8)*APS + ks2*8 + tg    ];
                pa[2] = myP[(mt*16 + grp    )*APS + ks2*8 + tg + 4];
                pa[3] = myP[(mt*16 + grp + 8)*APS + ks2*8 + tg + 4];
#pragma unroll
                for (int nt = 0; nt < 8; nt++)
                    mma_tf32(o[mt][nt], pa, vb[nt]);
            }
        }
        __syncwarp();
    }

    uint32_t* obase = O + (size_t)b*TT*CC + h*HD;
#pragma unroll
    for (int mt = 0; mt < 2; mt++) {
        int ra = q0 + mt*16 + grp;
        int rb = ra + 8;
        float inv0 = 1.f / lrow[mt][0];
        float inv1 = 1.f / lrow[mt][1];
#pragma unroll
        for (int nt = 0; nt < 8; nt++) {
            int d = nt*8 + 2*tg;
            uint2 w0 = {f2tf(o[mt][nt][0]*inv0), f2tf(o[mt][nt][1]*inv0)};
            uint2 w1 = {f2tf(o[mt][nt][2]*inv1), f2tf(o[mt][nt][3]*inv1)};
            *(uint2*)(obase + (size_t)ra*CC + d) = w0;
            *(uint2*)(obase + (size_t)rb*CC + d) = w1;
        }
    }
}

// ---------------------------------------------------------------------------
// Host
// ---------------------------------------------------------------------------
static void cvt(const float* src, uint32_t* dst, int n) {
    int n4 = n / 4;
    cvt_kernel<<<(n4 + 255)/256, 256>>>(src, dst, n4);
}

extern "C" void kernel_launch(void* const* d_in, const int* in_sizes, int n_in,
                              void* d_out, int out_size)
{
    (void)in_sizes; (void)n_in; (void)out_size;

    const int*   idx     = (const int*)  d_in[0];
    const float* tok_emb = (const float*)d_in[1];
    const float* pos_emb = (const float*)d_in[2];
    const float* ln1_g   = (const float*)d_in[3];
    const float* ln1_b   = (const float*)d_in[4];
    const float* wq      = (const float*)d_in[5];
    const float* wk      = (const float*)d_in[6];
    const float* wv      = (const float*)d_in[7];
    const float* wo      = (const float*)d_in[8];
    const float* wo_b    = (const float*)d_in[9];
    const float* ln2_g   = (const float*)d_in[10];
    const float* ln2_b   = (const float*)d_in[11];
    const float* w1      = (const float*)d_in[12];
    const float* b1      = (const float*)d_in[13];
    const float* w2      = (const float*)d_in[14];
    const float* b2      = (const float*)d_in[15];
    const float* lnf_g   = (const float*)d_in[16];
    const float* lnf_b   = (const float*)d_in[17];
    const float* lm_w    = (const float*)d_in[18];
    const float* lm_b    = (const float*)d_in[19];
    float* out = (float*)d_out;

    float *x;
    uint32_t *h, *q, *k, *v, *att, *u, *wt;
    cudaGetSymbolAddress((void**)&x,   g_x);
    cudaGetSymbolAddress((void**)&h,   g_h);
    cudaGetSymbolAddress((void**)&q,   g_q);
    cudaGetSymbolAddress((void**)&k,   g_k);
    cudaGetSymbolAddress((void**)&v,   g_v);
    cudaGetSymbolAddress((void**)&att, g_att);
    cudaGetSymbolAddress((void**)&u,   g_u);
    cudaGetSymbolAddress((void**)&wt,  g_wt);

    cudaFuncSetAttribute(attn_mma, cudaFuncAttributeMaxDynamicSharedMemorySize, ATT_SMEM);
    cudaFuncSetAttribute(tgemm<false,false,false>, cudaFuncAttributeMaxDynamicSharedMemorySize, SMEM_GEMM);
    cudaFuncSetAttribute(tgemm<false,true ,false>, cudaFuncAttributeMaxDynamicSharedMemorySize, SMEM_GEMM);
    cudaFuncSetAttribute(tgemm<true ,false,true >, cudaFuncAttributeMaxDynamicSharedMemorySize, SMEM_GEMM);
    cudaFuncSetAttribute(qkv_gemm,                 cudaFuncAttributeMaxDynamicSharedMemorySize, SMEM_GEMM);
    cudaFuncSetAttribute(tgemm_big,                cudaFuncAttributeMaxDynamicSharedMemorySize, SMEM_GEMM_BIG);

    // Pre-convert all weights to tf32
    cvt(wq,   wt + OFF_WQ, LL*CC*CC);
    cvt(wk,   wt + OFF_WK, LL*CC*CC);
    cvt(wv,   wt + OFF_WV, LL*CC*CC);
    cvt(wo,   wt + OFF_WO, LL*CC*CC);
    cvt(w1,   wt + OFF_W1, LL*CC*FF);
    cvt(w2,   wt + OFF_W2, LL*FF*CC);
    cvt(lm_w, wt + OFF_LM, CC*VV);

    {
        int total = MM * (CC/4);
        embed_kernel<<<(total + 255)/256, 256>>>(idx, tok_emb, pos_emb, x);
    }

    for (int L = 0; L < LL; L++) {
        const float* g1  = ln1_g + (size_t)L*CC;
        const float* bg1 = ln1_b + (size_t)L*CC;
        const uint32_t* Wq = wt + OFF_WQ + (size_t)L*CC*CC;
        const uint32_t* Wk = wt + OFF_WK + (size_t)L*CC*CC;
        const uint32_t* Wv = wt + OFF_WV + (size_t)L*CC*CC;
        const uint32_t* Wo = wt + OFF_WO + (size_t)L*CC*CC;
        const float* Wob = wo_b + (size_t)L*CC;
        const float* g2  = ln2_g + (size_t)L*CC;
        const float* bg2 = ln2_b + (size_t)L*CC;
        const uint32_t* W1 = wt + OFF_W1 + (size_t)L*CC*FF;
        const float* B1  = b1 + (size_t)L*FF;
        const uint32_t* W2 = wt + OFF_W2 + (size_t)L*FF*CC;
        const float* B2  = b2 + (size_t)L*CC;

        ln_kernel<<<MM/8, 256>>>(x, g1, bg1, h);
        qkv_gemm<<<dim3(9, 64), 128, SMEM_GEMM>>>(h, Wq, Wk, Wv, q, k, v);
        attn_mma<<<BB*NH, 256, ATT_SMEM>>>(q, k, v, att);
        // x += att @ Wo + wo_b
        tgemm<false,true,false><<<dim3(CC/128, MM/128), 128, SMEM_GEMM>>>(
            att, Wo, Wob, x, x, MM, CC, CC);
        ln_kernel<<<MM/8, 256>>>(x, g2, bg2, h);
        // u = relu(h @ W1 + b1), tf32 out
        tgemm<true,false,true><<<dim3(FF/128, MM/128), 128, SMEM_GEMM>>>(
            h, W1, B1, nullptr, u, MM, FF, CC);
        // x += u @ W2 + b2
        tgemm<false,true,false><<<dim3(CC/128, MM/128), 128, SMEM_GEMM>>>(
            u, W2, B2, x, x, MM, CC, FF);
    }

    ln_kernel<<<MM/8, 256>>>(x, lnf_g, lnf_b, h);
    // logits = h @ lm_w + lm_b  (big-M tile kernel)
    tgemm_big<<<dim3(VV/128, MM/256), 256, SMEM_GEMM_BIG>>>(
        h, wt + OFF_LM, lm_b, out, MM, VV, CC);
}

// round 8
// speedup vs baseline: 1.0283x; 1.0283x over previous
#include <cuda_runtime.h>
#include <math.h>
#include <stdint.h>

// Problem dims
#define BB 32
#define TT 256
#define CC 384
#define LL 6
#define NH 6
#define HD 64
#define VV 32000
#define MM (BB*TT)      // 8192
#define FF (4*CC)       // 1536

// tf32 weight scratch layout (element offsets)
#define OFF_WQ 0
#define OFF_WK 884736
#define OFF_WV 1769472
#define OFF_WO 2654208
#define OFF_W1 3538944
#define OFF_W2 7077888
#define OFF_LM 10616832
#define WT_TOTAL 22904832

// Scratch (device globals; no allocations allowed)
__device__ float    g_x[MM*CC];          // residual stream (f32)
__device__ uint32_t g_h[MM*CC];          // LN output (tf32)
__device__ uint32_t g_q[MM*CC];
__device__ uint32_t g_k[MM*CC];
__device__ uint32_t g_v[MM*CC];
__device__ uint32_t g_att[MM*CC];
__device__ uint32_t g_u[MM*FF];
__device__ uint32_t g_wt[WT_TOTAL];      // tf32 weights

// ---------------------------------------------------------------------------
// Helpers
// ---------------------------------------------------------------------------
__device__ __forceinline__ uint32_t f2tf(float f) {
    uint32_t u;
    asm("cvt.rna.tf32.f32 %0, %1;" : "=r"(u) : "f"(f));
    return u;
}

__device__ __forceinline__ void mma_tf32(float* c, const uint32_t* a, const uint32_t* b) {
    asm volatile(
        "mma.sync.aligned.m16n8k8.row.col.f32.tf32.tf32.f32 "
        "{%0,%1,%2,%3}, {%4,%5,%6,%7}, {%8,%9}, {%0,%1,%2,%3};"
        : "+f"(c[0]), "+f"(c[1]), "+f"(c[2]), "+f"(c[3])
        : "r"(a[0]), "r"(a[1]), "r"(a[2]), "r"(a[3]),
          "r"(b[0]), "r"(b[1]));
}

__device__ __forceinline__ void cp_async16(void* sptr, const void* gptr) {
    uint32_t sa = (uint32_t)__cvta_generic_to_shared(sptr);
    asm volatile("cp.async.cg.shared.global [%0], [%1], 16;\n" :: "r"(sa), "l"(gptr));
}
#define CP_COMMIT() asm volatile("cp.async.commit_group;\n" ::: "memory")
#define CP_WAIT0()  asm volatile("cp.async.wait_group 0;\n" ::: "memory")

// ---------------------------------------------------------------------------
// f32 -> tf32 conversion (vectorized by 4)
// ---------------------------------------------------------------------------
__global__ void cvt_kernel(const float* __restrict__ src, uint32_t* __restrict__ dst, int n4)
{
    int i = blockIdx.x * blockDim.x + threadIdx.x;
    if (i >= n4) return;
    float4 v = *(const float4*)(src + (size_t)i*4);
    uint4 u;
    u.x = f2tf(v.x); u.y = f2tf(v.y); u.z = f2tf(v.z); u.w = f2tf(v.w);
    *(uint4*)(dst + (size_t)i*4) = u;
}

// ---------------------------------------------------------------------------
// Embedding (f32 residual stream)
// ---------------------------------------------------------------------------
__global__ void embed_kernel(const int* __restrict__ idx,
                             const float* __restrict__ tok,
                             const float* __restrict__ pos,
                             float* __restrict__ X)
{
    int i = blockIdx.x * blockDim.x + threadIdx.x;
    if (i >= MM * (CC/4)) return;
    int row = i / (CC/4);
    int c4  = i % (CC/4);
    int t   = idx[row];
    int p   = row & (TT-1);
    float4 a = *(const float4*)(tok + (size_t)t*CC + c4*4);
    float4 e = *(const float4*)(pos + (size_t)p*CC + c4*4);
    a.x += e.x; a.y += e.y; a.z += e.z; a.w += e.w;
    *(float4*)(X + (size_t)row*CC + c4*4) = a;
}

// ---------------------------------------------------------------------------
// LayerNorm: one warp per row; output tf32
// ---------------------------------------------------------------------------
__global__ void ln_kernel(const float* __restrict__ X,
                          const float* __restrict__ g,
                          const float* __restrict__ b,
                          uint32_t* __restrict__ Y)
{
    int row  = blockIdx.x * 8 + (threadIdx.x >> 5);
    int lane = threadIdx.x & 31;
    if (row >= MM) return;
    const float* x = X + (size_t)row*CC;
    float v[12];
    float s = 0.f, ss = 0.f;
#pragma unroll
    for (int i = 0; i < 12; i++) {
        v[i] = x[lane + i*32];
        s  += v[i];
        ss += v[i]*v[i];
    }
#pragma unroll
    for (int o = 16; o; o >>= 1) {
        s  += __shfl_xor_sync(0xFFFFFFFFu, s,  o);
        ss += __shfl_xor_sync(0xFFFFFFFFu, ss, o);
    }
    float mean = s  * (1.0f/CC);
    float var  = ss * (1.0f/CC) - mean*mean;
    float inv  = rsqrtf(var + 1e-5f);
    uint32_t* y = Y + (size_t)row*CC;
#pragma unroll
    for (int i = 0; i < 12; i++) {
        int c = lane + i*32;
        y[c] = f2tf((v[i]-mean)*inv*g[c] + b[c]);
    }
}

// ---------------------------------------------------------------------------
// TF32 GEMM (layer, round-6 proven): 128x128 tile, BK=32, 128 threads,
// warp tile 64x64, 2-stage cp.async double buffer.
// ---------------------------------------------------------------------------
struct GemmSmem {
    uint32_t As[2][128][36];
    uint32_t Bs[2][32][136];
};
#define SMEM_GEMM ((int)sizeof(GemmSmem))   // 71680 bytes

template<bool RELU, bool RES, bool OUTTF>
__device__ __forceinline__
void gemm_core(GemmSmem* sm,
               const uint32_t* __restrict__ A, const uint32_t* __restrict__ B,
               const float* __restrict__ bias, const float* __restrict__ res,
               void* __restrict__ Cv, int M, int N, int K, int bm, int bn)
{
    const int tid  = threadIdx.x;
    const int lane = tid & 31;
    const int wid  = tid >> 5;
    const int wm = (wid & 1) * 64;
    const int wn = (wid >> 1) * 64;
    const int grp = lane >> 2;
    const int tg  = lane & 3;

    float acc[4][8][4];
#pragma unroll
    for (int mt = 0; mt < 4; mt++)
#pragma unroll
        for (int nt = 0; nt < 8; nt++)
#pragma unroll
            for (int e = 0; e < 4; e++) acc[mt][nt][e] = 0.f;

    auto issue = [&](int s, int k0) {
#pragma unroll
        for (int p = 0; p < 8; p++) {
            int i  = tid + p*128;
            int r  = i >> 3;
            int c4 = (i & 7) * 4;
            cp_async16(&sm->As[s][r][c4], A + (size_t)(bm + r)*K + k0 + c4);
        }
#pragma unroll
        for (int p = 0; p < 8; p++) {
            int i  = tid + p*128;
            int r  = i >> 5;
            int c4 = (i & 31) * 4;
            cp_async16(&sm->Bs[s][r][c4], B + (size_t)(k0 + r)*N + bn + c4);
        }
        CP_COMMIT();
    };

    const int nIter = K >> 5;
    issue(0, 0);

    for (int it = 0; it < nIter; it++) {
        const int cur = it & 1;
        CP_WAIT0();
        __syncthreads();
        if (it + 1 < nIter) issue(cur ^ 1, (it + 1) << 5);

#pragma unroll
        for (int kk = 0; kk < 32; kk += 8) {
            uint32_t af[4][4], bf[8][2];
#pragma unroll
            for (int mt = 0; mt < 4; mt++) {
                int r = wm + mt*16 + grp;
                af[mt][0] = sm->As[cur][r    ][kk + tg    ];
                af[mt][1] = sm->As[cur][r + 8][kk + tg    ];
                af[mt][2] = sm->As[cur][r    ][kk + tg + 4];
                af[mt][3] = sm->As[cur][r + 8][kk + tg + 4];
            }
#pragma unroll
            for (int nt = 0; nt < 8; nt++) {
                int c = wn + nt*8 + grp;
                bf[nt][0] = sm->Bs[cur][kk + tg    ][c];
                bf[nt][1] = sm->Bs[cur][kk + tg + 4][c];
            }
#pragma unroll
            for (int mt = 0; mt < 4; mt++)
#pragma unroll
                for (int nt = 0; nt < 8; nt++)
                    mma_tf32(acc[mt][nt], af[mt], bf[nt]);
        }
    }

    // Epilogue
#pragma unroll
    for (int mt = 0; mt < 4; mt++) {
        int r0 = bm + wm + mt*16 + grp;
        int r1 = r0 + 8;
#pragma unroll
        for (int nt = 0; nt < 8; nt++) {
            int c = bn + wn + nt*8 + tg*2;
            float o0x = acc[mt][nt][0], o0y = acc[mt][nt][1];
            float o1x = acc[mt][nt][2], o1y = acc[mt][nt][3];
            if (bias) {
                float bv0 = bias[c], bv1 = bias[c+1];
                o0x += bv0; o0y += bv1; o1x += bv0; o1y += bv1;
            }
            if (RES) {
                float2 ra = *(const float2*)(res + (size_t)r0*N + c);
                float2 rb = *(const float2*)(res + (size_t)r1*N + c);
                o0x += ra.x; o0y += ra.y; o1x += rb.x; o1y += rb.y;
            }
            if (RELU) {
                o0x = fmaxf(o0x, 0.f); o0y = fmaxf(o0y, 0.f);
                o1x = fmaxf(o1x, 0.f); o1y = fmaxf(o1y, 0.f);
            }
            if (OUTTF) {
                uint32_t* C = (uint32_t*)Cv;
                uint2 w0 = {f2tf(o0x), f2tf(o0y)};
                uint2 w1 = {f2tf(o1x), f2tf(o1y)};
                *(uint2*)(C + (size_t)r0*N + c) = w0;
                *(uint2*)(C + (size_t)r1*N + c) = w1;
            } else {
                float* C = (float*)Cv;
                float2 w0 = {o0x, o0y};
                float2 w1 = {o1x, o1y};
                *(float2*)(C + (size_t)r0*N + c) = w0;
                *(float2*)(C + (size_t)r1*N + c) = w1;
            }
        }
    }
}

template<bool RELU, bool RES, bool OUTTF>
__global__ __launch_bounds__(128)
void tgemm(const uint32_t* __restrict__ A, const uint32_t* __restrict__ B,
           const float* __restrict__ bias, const float* __restrict__ res,
           void* __restrict__ C, int M, int N, int K)
{
    extern __shared__ GemmSmem smg[];
    gemm_core<RELU, RES, OUTTF>(smg, A, B, bias, res, C, M, N, K,
                                blockIdx.y * 128, blockIdx.x * 128);
}

// Fused QKV: grid.x = 9 (3 matrices x 3 col-tiles), grid.y = 64. tf32 out.
__global__ __launch_bounds__(128)
void qkv_gemm(const uint32_t* __restrict__ A,
              const uint32_t* __restrict__ Wq, const uint32_t* __restrict__ Wk,
              const uint32_t* __restrict__ Wv,
              uint32_t* __restrict__ Q, uint32_t* __restrict__ Ko, uint32_t* __restrict__ V)
{
    extern __shared__ GemmSmem smg[];
    int sel = blockIdx.x / 3;
    int bn  = (blockIdx.x % 3) * 128;
    const uint32_t* B = (sel == 0) ? Wq : (sel == 1) ? Wk : Wv;
    uint32_t*       C = (sel == 0) ? Q  : (sel == 1) ? Ko : V;
    gemm_core<false, false, true>(smg, A, B, nullptr, nullptr, C,
                                  MM, CC, CC, blockIdx.y * 128, bn);
}

// ---------------------------------------------------------------------------
// Big-M GEMM for LM head: 256x128 tile, BK=32, 256 threads (8 warps, 4x2 of
// 64x64), 2-stage cp.async. Halves A re-reads through L2 vs 128x128.
// ---------------------------------------------------------------------------
struct GemmSmemBig {
    uint32_t As[2][256][36];
    uint32_t Bs[2][32][136];
};
#define SMEM_GEMM_BIG ((int)sizeof(GemmSmemBig))   // 108544 bytes

__global__ __launch_bounds__(256)
void tgemm_big(const uint32_t* __restrict__ A, const uint32_t* __restrict__ B,
               const float* __restrict__ bias, float* __restrict__ C,
               int M, int N, int K)
{
    extern __shared__ GemmSmemBig smb[];
    GemmSmemBig* sm = smb;

    const int bm = blockIdx.y * 256;
    const int bn = blockIdx.x * 128;
    const int tid  = threadIdx.x;
    const int lane = tid & 31;
    const int wid  = tid >> 5;
    const int wm = (wid & 3) * 64;
    const int wn = (wid >> 2) * 64;
    const int grp = lane >> 2;
    const int tg  = lane & 3;

    float acc[4][8][4];
#pragma unroll
    for (int mt = 0; mt < 4; mt++)
#pragma unroll
        for (int nt = 0; nt < 8; nt++)
#pragma unroll
            for (int e = 0; e < 4; e++) acc[mt][nt][e] = 0.f;

    auto issue = [&](int s, int k0) {
#pragma unroll
        for (int p = 0; p < 8; p++) {
            int i  = tid + p*256;
            int r  = i >> 3;
            int c4 = (i & 7) * 4;
            cp_async16(&sm->As[s][r][c4], A + (size_t)(bm + r)*K + k0 + c4);
        }
#pragma unroll
        for (int p = 0; p < 4; p++) {
            int i  = tid + p*256;
            int r  = i >> 5;
            int c4 = (i & 31) * 4;
            cp_async16(&sm->Bs[s][r][c4], B + (size_t)(k0 + r)*N + bn + c4);
        }
        CP_COMMIT();
    };

    const int nIter = K >> 5;
    issue(0, 0);

    for (int it = 0; it < nIter; it++) {
        const int cur = it & 1;
        CP_WAIT0();
        __syncthreads();
        if (it + 1 < nIter) issue(cur ^ 1, (it + 1) << 5);

#pragma unroll
        for (int kk = 0; kk < 32; kk += 8) {
            uint32_t af[4][4], bf[8][2];
#pragma unroll
            for (int mt = 0; mt < 4; mt++) {
                int r = wm + mt*16 + grp;
                af[mt][0] = sm->As[cur][r    ][kk + tg    ];
                af[mt][1] = sm->As[cur][r + 8][kk + tg    ];
                af[mt][2] = sm->As[cur][r    ][kk + tg + 4];
                af[mt][3] = sm->As[cur][r + 8][kk + tg + 4];
            }
#pragma unroll
            for (int nt = 0; nt < 8; nt++) {
                int c = wn + nt*8 + grp;
                bf[nt][0] = sm->Bs[cur][kk + tg    ][c];
                bf[nt][1] = sm->Bs[cur][kk + tg + 4][c];
            }
#pragma unroll
            for (int mt = 0; mt < 4; mt++)
#pragma unroll
                for (int nt = 0; nt < 8; nt++)
                    mma_tf32(acc[mt][nt], af[mt], bf[nt]);
        }
    }

#pragma unroll
    for (int mt = 0; mt < 4; mt++) {
        int r0 = bm + wm + mt*16 + grp;
        int r1 = r0 + 8;
#pragma unroll
        for (int nt = 0; nt < 8; nt++) {
            int c = bn + wn + nt*8 + tg*2;
            float bv0 = bias[c], bv1 = bias[c+1];
            float2 w0 = {acc[mt][nt][0] + bv0, acc[mt][nt][1] + bv1};
            float2 w1 = {acc[mt][nt][2] + bv0, acc[mt][nt][3] + bv1};
            *(float2*)(C + (size_t)r0*N + c) = w0;
            *(float2*)(C + (size_t)r1*N + c) = w1;
        }
    }
}

// ---------------------------------------------------------------------------
// Tensor-core flash attention; q/k/v tf32, att output tf32.
// ---------------------------------------------------------------------------
#define AKS 68
#define AVS 72
#define APS 36
#define ATT_SMEM ((TT*AKS + TT*AVS + 8*32*APS) * (int)sizeof(uint32_t))

__global__ __launch_bounds__(256, 1)
void attn_mma(const uint32_t* __restrict__ Q, const uint32_t* __restrict__ K,
              const uint32_t* __restrict__ V, uint32_t* __restrict__ O)
{
    extern __shared__ uint32_t sm[];
    uint32_t* Ks = sm;
    uint32_t* Vs = sm + TT*AKS;
    uint32_t* Pb = sm + TT*AKS + TT*AVS;

    const int bh = blockIdx.x;
    const int b  = bh / NH;
    const int h  = bh % NH;
    const float scale = 0.05103103630798288f;  // 1/sqrt(384)

    const int tid = threadIdx.x;
    const uint32_t* kbase = K + (size_t)b*TT*CC + h*HD;
    const uint32_t* vbase = V + (size_t)b*TT*CC + h*HD;

    for (int i = tid; i < TT*16; i += 256) {
        int t  = i >> 4;
        int d4 = (i & 15) * 4;
        *(uint4*)&Ks[t*AKS + d4] = *(const uint4*)(kbase + (size_t)t*CC + d4);
        *(uint4*)&Vs[t*AVS + d4] = *(const uint4*)(vbase + (size_t)t*CC + d4);
    }
    __syncthreads();

    const int lane = tid & 31;
    const int w    = tid >> 5;
    const int grp  = lane >> 2;
    const int tg   = lane & 3;
    const int q0   = w * 32;

    const uint32_t* qbase = Q + (size_t)b*TT*CC + h*HD;
    uint32_t qa[2][8][4];
#pragma unroll
    for (int mt = 0; mt < 2; mt++) {
        int ra = q0 + mt*16 + grp;
        int rb = ra + 8;
#pragma unroll
        for (int ks = 0; ks < 8; ks++) {
            int d = ks*8 + tg;
            qa[mt][ks][0] = qbase[(size_t)ra*CC + d    ];
            qa[mt][ks][1] = qbase[(size_t)rb*CC + d    ];
            qa[mt][ks][2] = qbase[(size_t)ra*CC + d + 4];
            qa[mt][ks][3] = qbase[(size_t)rb*CC + d + 4];
        }
    }

    float o[2][8][4];
#pragma unroll
    for (int mt = 0; mt < 2; mt++)
#pragma unroll
        for (int nt = 0; nt < 8; nt++)
#pragma unroll
            for (int e = 0; e < 4; e++) o[mt][nt][e] = 0.f;

    float mrow[2][2] = {{-1e30f,-1e30f},{-1e30f,-1e30f}};
    float lrow[2][2] = {{0.f,0.f},{0.f,0.f}};

    uint32_t* myP = Pb + w * 32 * APS;

    for (int j = 0; j <= w; j++) {
        const int kbeg = j * 32;
        float s[2][4][4];
#pragma unroll
        for (int mt = 0; mt < 2; mt++)
#pragma unroll
            for (int nt = 0; nt < 4; nt++)
#pragma unroll
                for (int e = 0; e < 4; e++) s[mt][nt][e] = 0.f;

#pragma unroll
        for (int ks = 0; ks < 8; ks++) {
            uint32_t bf[4][2];
#pragma unroll
            for (int nt = 0; nt < 4; nt++) {
                int key = kbeg + nt*8 + grp;
                int d   = ks*8 + tg;
                bf[nt][0] = Ks[key*AKS + d    ];
                bf[nt][1] = Ks[key*AKS + d + 4];
            }
#pragma unroll
            for (int mt = 0; mt < 2; mt++)
#pragma unroll
                for (int nt = 0; nt < 4; nt++)
                    mma_tf32(s[mt][nt], qa[mt][ks], bf[nt]);
        }

#pragma unroll
        for (int mt = 0; mt < 2; mt++) {
            int ra = q0 + mt*16 + grp;
            int rb = ra + 8;
            float rmax0 = -1e30f, rmax1 = -1e30f;
#pragma unroll
            for (int nt = 0; nt < 4; nt++) {
                int c0 = kbeg + nt*8 + 2*tg;
#pragma unroll
                for (int e = 0; e < 4; e++) {
                    float vv = s[mt][nt][e] * scale;
                    int col = c0 + (e & 1);
                    int row = (e < 2) ? ra : rb;
                    if (j == w && col > row) vv = -1e30f;
                    s[mt][nt][e] = vv;
                }
                rmax0 = fmaxf(rmax0, fmaxf(s[mt][nt][0], s[mt][nt][1]));
                rmax1 = fmaxf(rmax1, fmaxf(s[mt][nt][2], s[mt][nt][3]));
            }
            rmax0 = fmaxf(rmax0, __shfl_xor_sync(0xFFFFFFFFu, rmax0, 1));
            rmax0 = fmaxf(rmax0, __shfl_xor_sync(0xFFFFFFFFu, rmax0, 2));
            rmax1 = fmaxf(rmax1, __shfl_xor_sync(0xFFFFFFFFu, rmax1, 1));
            rmax1 = fmaxf(rmax1, __shfl_xor_sync(0xFFFFFFFFu, rmax1, 2));

            float mn0 = fmaxf(mrow[mt][0], rmax0);
            float mn1 = fmaxf(mrow[mt][1], rmax1);
            float cr0 = __expf(mrow[mt][0] - mn0);
            float cr1 = __expf(mrow[mt][1] - mn1);
            mrow[mt][0] = mn0; mrow[mt][1] = mn1;

            float rs0 = 0.f, rs1 = 0.f;
#pragma unroll
            for (int nt = 0; nt < 4; nt++) {
                float p0 = __expf(s[mt][nt][0] - mn0);
                float p1 = __expf(s[mt][nt][1] - mn0);
                float p2 = __expf(s[mt][nt][2] - mn1);
                float p3 = __expf(s[mt][nt][3] - mn1);
                rs0 += p0 + p1; rs1 += p2 + p3;
                int cb = nt*8 + 2*tg;
                myP[(mt*16 + grp    )*APS + cb    ] = f2tf(p0);
                myP[(mt*16 + grp    )*APS + cb + 1] = f2tf(p1);
                myP[(mt*16 + grp + 8)*APS + cb    ] = f2tf(p2);
                myP[(mt*16 + grp + 8)*APS + cb + 1] = f2tf(p3);
            }
            rs0 += __shfl_xor_sync(0xFFFFFFFFu, rs0, 1);
            rs0 += __shfl_xor_sync(0xFFFFFFFFu, rs0, 2);
            rs1 += __shfl_xor_sync(0xFFFFFFFFu, rs1, 1);
            rs1 += __shfl_xor_sync(0xFFFFFFFFu, rs1, 2);
            lrow[mt][0] = lrow[mt][0]*cr0 + rs0;
            lrow[mt][1] = lrow[mt][1]*cr1 + rs1;
#pragma unroll
            for (int nt = 0; nt < 8; nt++) {
                o[mt][nt][0] *= cr0; o[mt][nt][1] *= cr0;
                o[mt][nt][2] *= cr1; o[mt][nt][3] *= cr1;
            }
        }
        __syncwarp();

#pragma unroll
        for (int ks2 = 0; ks2 < 4; ks2++) {
            uint32_t vb[8][2];
#pragma unroll
            for (int nt = 0; nt < 8; nt++) {
                int key = kbeg + ks2*8 + tg;
                int d   = nt*8 + grp;
                vb[nt][0] = Vs[ key     *AVS + d];
                vb[nt][1] = Vs[(key + 4)*AVS + d];
            }
#pragma unroll
            for (int mt = 0; mt < 2; mt++) {
                uint32_t pa[4];
                pa[0] = myP[(mt*16 + grp    )*APS + ks2*8 + tg    ];
                pa[1] = myP[(mt*16 + grp + 8)*APS + ks2*8 + tg    ];
                pa[2] = myP[(mt*16 + grp    )*APS + ks2*8 + tg + 4];
                pa[3] = myP[(mt*16 + grp + 8)*APS + ks2*8 + tg + 4];
#pragma unroll
                for (int nt = 0; nt < 8; nt++)
                    mma_tf32(o[mt][nt], pa, vb[nt]);
            }
        }
        __syncwarp();
    }

    uint32_t* obase = O + (size_t)b*TT*CC + h*HD;
#pragma unroll
    for (int mt = 0; mt < 2; mt++) {
        int ra = q0 + mt*16 + grp;
        int rb = ra + 8;
        float inv0 = 1.f / lrow[mt][0];
        float inv1 = 1.f / lrow[mt][1];
#pragma unroll
        for (int nt = 0; nt < 8; nt++) {
            int d = nt*8 + 2*tg;
            uint2 w0 = {f2tf(o[mt][nt][0]*inv0), f2tf(o[mt][nt][1]*inv0)};
            uint2 w1 = {f2tf(o[mt][nt][2]*inv1), f2tf(o[mt][nt][3]*inv1)};
            *(uint2*)(obase + (size_t)ra*CC + d) = w0;
            *(uint2*)(obase + (size_t)rb*CC + d) = w1;
        }
    }
}

// ---------------------------------------------------------------------------
// Host
// ---------------------------------------------------------------------------
static void cvt(const float* src, uint32_t* dst, int n) {
    int n4 = n / 4;
    cvt_kernel<<<(n4 + 255)/256, 256>>>(src, dst, n4);
}

extern "C" void kernel_launch(void* const* d_in, const int* in_sizes, int n_in,
                              void* d_out, int out_size)
{
    (void)in_sizes; (void)n_in; (void)out_size;

    const int*   idx     = (const int*)  d_in[0];
    const float* tok_emb = (const float*)d_in[1];
    const float* pos_emb = (const float*)d_in[2];
    const float* ln1_g   = (const float*)d_in[3];
    const float* ln1_b   = (const float*)d_in[4];
    const float* wq      = (const float*)d_in[5];
    const float* wk      = (const float*)d_in[6];
    const float* wv      = (const float*)d_in[7];
    const float* wo      = (const float*)d_in[8];
    const float* wo_b    = (const float*)d_in[9];
    const float* ln2_g   = (const float*)d_in[10];
    const float* ln2_b   = (const float*)d_in[11];
    const float* w1      = (const float*)d_in[12];
    const float* b1      = (const float*)d_in[13];
    const float* w2      = (const float*)d_in[14];
    const float* b2      = (const float*)d_in[15];
    const float* lnf_g   = (const float*)d_in[16];
    const float* lnf_b   = (const float*)d_in[17];
    const float* lm_w    = (const float*)d_in[18];
    const float* lm_b    = (const float*)d_in[19];
    float* out = (float*)d_out;

    float *x;
    uint32_t *h, *q, *k, *v, *att, *u, *wt;
    cudaGetSymbolAddress((void**)&x,   g_x);
    cudaGetSymbolAddress((void**)&h,   g_h);
    cudaGetSymbolAddress((void**)&q,   g_q);
    cudaGetSymbolAddress((void**)&k,   g_k);
    cudaGetSymbolAddress((void**)&v,   g_v);
    cudaGetSymbolAddress((void**)&att, g_att);
    cudaGetSymbolAddress((void**)&u,   g_u);
    cudaGetSymbolAddress((void**)&wt,  g_wt);

    cudaFuncSetAttribute(attn_mma, cudaFuncAttributeMaxDynamicSharedMemorySize, ATT_SMEM);
    cudaFuncSetAttribute(tgemm<false,false,false>, cudaFuncAttributeMaxDynamicSharedMemorySize, SMEM_GEMM);
    cudaFuncSetAttribute(tgemm<false,true ,false>, cudaFuncAttributeMaxDynamicSharedMemorySize, SMEM_GEMM);
    cudaFuncSetAttribute(tgemm<true ,false,true >, cudaFuncAttributeMaxDynamicSharedMemorySize, SMEM_GEMM);
    cudaFuncSetAttribute(qkv_gemm,                 cudaFuncAttributeMaxDynamicSharedMemorySize, SMEM_GEMM);
    cudaFuncSetAttribute(tgemm_big,                cudaFuncAttributeMaxDynamicSharedMemorySize, SMEM_GEMM_BIG);

    // Pre-convert all weights to tf32
    cvt(wq,   wt + OFF_WQ, LL*CC*CC);
    cvt(wk,   wt + OFF_WK, LL*CC*CC);
    cvt(wv,   wt + OFF_WV, LL*CC*CC);
    cvt(wo,   wt + OFF_WO, LL*CC*CC);
    cvt(w1,   wt + OFF_W1, LL*CC*FF);
    cvt(w2,   wt + OFF_W2, LL*FF*CC);
    cvt(lm_w, wt + OFF_LM, CC*VV);

    {
        int total = MM * (CC/4);
        embed_kernel<<<(total + 255)/256, 256>>>(idx, tok_emb, pos_emb, x);
    }

    for (int L = 0; L < LL; L++) {
        const float* g1  = ln1_g + (size_t)L*CC;
        const float* bg1 = ln1_b + (size_t)L*CC;
        const uint32_t* Wq = wt + OFF_WQ + (size_t)L*CC*CC;
        const uint32_t* Wk = wt + OFF_WK + (size_t)L*CC*CC;
        const uint32_t* Wv = wt + OFF_WV + (size_t)L*CC*CC;
        const uint32_t* Wo = wt + OFF_WO + (size_t)L*CC*CC;
        const float* Wob = wo_b + (size_t)L*CC;
        const float* g2  = ln2_g + (size_t)L*CC;
        const float* bg2 = ln2_b + (size_t)L*CC;
        const uint32_t* W1 = wt + OFF_W1 + (size_t)L*CC*FF;
        const float* B1  = b1 + (size_t)L*FF;
        const uint32_t* W2 = wt + OFF_W2 + (size_t)L*FF*CC;
        const float* B2  = b2 + (size_t)L*CC;

        ln_kernel<<<MM/8, 256>>>(x, g1, bg1, h);
        qkv_gemm<<<dim3(9, 64), 128, SMEM_GEMM>>>(h, Wq, Wk, Wv, q, k, v);
        attn_mma<<<BB*NH, 256, ATT_SMEM>>>(q, k, v, att);
        // x += att @ Wo + wo_b
        tgemm<false,true,false><<<dim3(CC/128, MM/128), 128, SMEM_GEMM>>>(
            att, Wo, Wob, x, x, MM, CC, CC);
        ln_kernel<<<MM/8, 256>>>(x, g2, bg2, h);
        // u = relu(h @ W1 + b1), tf32 out
        tgemm<true,false,true><<<dim3(FF/128, MM/128), 128, SMEM_GEMM>>>(
            h, W1, B1, nullptr, u, MM, FF, CC);
        // x += u @ W2 + b2
        tgemm<false,true,false><<<dim3(CC/128, MM/128), 128, SMEM_GEMM>>>(
            u, W2, B2, x, x, MM, CC, FF);
    }

    ln_kernel<<<MM/8, 256>>>(x, lnf_g, lnf_b, h);
    // logits = h @ lm_w + lm_b  (big-M tile kernel)
    tgemm_big<<<dim3(VV/128, MM/256), 256, SMEM_GEMM_BIG>>>(
        h, wt + OFF_LM, lm_b, out, MM, VV, CC);
}

// round 9
// speedup vs baseline: 1.1248x; 1.0938x over previous
#include <cuda_runtime.h>
#include <math.h>
#include <stdint.h>

// Problem dims
#define BB 32
#define TT 256
#define CC 384
#define LL 6
#define NH 6
#define HD 64
#define VV 32000
#define MM (BB*TT)      // 8192
#define FF (4*CC)       // 1536

// tf32 weight scratch layout (element offsets)
#define OFF_WQ 0
#define OFF_WK 884736
#define OFF_WV 1769472
#define OFF_WO 2654208
#define OFF_W1 3538944
#define OFF_W2 7077888
#define OFF_LM 10616832
#define WT_TOTAL 22904832

// Scratch (device globals; no allocations allowed)
__device__ float    g_x[MM*CC];          // residual stream (f32)
__device__ uint32_t g_h[MM*CC];          // LN output (tf32)
__device__ uint32_t g_q[MM*CC];
__device__ uint32_t g_k[MM*CC];
__device__ uint32_t g_v[MM*CC];
__device__ uint32_t g_att[MM*CC];
__device__ uint32_t g_u[MM*FF];
__device__ uint32_t g_wt[WT_TOTAL];      // tf32 weights

// ---------------------------------------------------------------------------
// Helpers
// ---------------------------------------------------------------------------
__device__ __forceinline__ uint32_t f2tf(float f) {
    uint32_t u;
    asm("cvt.rna.tf32.f32 %0, %1;" : "=r"(u) : "f"(f));
    return u;
}

__device__ __forceinline__ void mma_tf32(float* c, const uint32_t* a, const uint32_t* b) {
    asm volatile(
        "mma.sync.aligned.m16n8k8.row.col.f32.tf32.tf32.f32 "
        "{%0,%1,%2,%3}, {%4,%5,%6,%7}, {%8,%9}, {%0,%1,%2,%3};"
        : "+f"(c[0]), "+f"(c[1]), "+f"(c[2]), "+f"(c[3])
        : "r"(a[0]), "r"(a[1]), "r"(a[2]), "r"(a[3]),
          "r"(b[0]), "r"(b[1]));
}

__device__ __forceinline__ void cp_async16(void* sptr, const void* gptr) {
    uint32_t sa = (uint32_t)__cvta_generic_to_shared(sptr);
    asm volatile("cp.async.cg.shared.global [%0], [%1], 16;\n" :: "r"(sa), "l"(gptr));
}
#define CP_COMMIT() asm volatile("cp.async.commit_group;\n" ::: "memory")
#define CP_WAIT0()  asm volatile("cp.async.wait_group 0;\n" ::: "memory")

// ---------------------------------------------------------------------------
// Fused f32 -> tf32 conversion of ALL weights, one launch.
// Flat float4 index over concatenated ranges.
// ---------------------------------------------------------------------------
#define CVT_N0 221184      // wq  (LL*CC*CC/4)
#define CVT_N1 442368      // +wk
#define CVT_N2 663552      // +wv
#define CVT_N3 884736      // +wo
#define CVT_N4 1769472     // +w1 (884736)
#define CVT_N5 2654208     // +w2 (884736)
#define CVT_N6 5726208     // +lm (3072000)

__global__ void cvt_all_kernel(const float* __restrict__ wq, const float* __restrict__ wk,
                               const float* __restrict__ wv, const float* __restrict__ wo,
                               const float* __restrict__ w1, const float* __restrict__ w2,
                               const float* __restrict__ lm, uint32_t* __restrict__ wt)
{
    int i = blockIdx.x * blockDim.x + threadIdx.x;
    if (i >= CVT_N6) return;
    const float* src;
    uint32_t* dst;
    int local;
    if (i < CVT_N0)      { src = wq; dst = wt + OFF_WQ; local = i; }
    else if (i < CVT_N1) { src = wk; dst = wt + OFF_WK; local = i - CVT_N0; }
    else if (i < CVT_N2) { src = wv; dst = wt + OFF_WV; local = i - CVT_N1; }
    else if (i < CVT_N3) { src = wo; dst = wt + OFF_WO; local = i - CVT_N2; }
    else if (i < CVT_N4) { src = w1; dst = wt + OFF_W1; local = i - CVT_N3; }
    else if (i < CVT_N5) { src = w2; dst = wt + OFF_W2; local = i - CVT_N4; }
    else                 { src = lm; dst = wt + OFF_LM; local = i - CVT_N5; }
    float4 v = *(const float4*)(src + (size_t)local*4);
    uint4 u;
    u.x = f2tf(v.x); u.y = f2tf(v.y); u.z = f2tf(v.z); u.w = f2tf(v.w);
    *(uint4*)(dst + (size_t)local*4) = u;
}

// ---------------------------------------------------------------------------
// Embedding (f32 residual stream)
// ---------------------------------------------------------------------------
__global__ void embed_kernel(const int* __restrict__ idx,
                             const float* __restrict__ tok,
                             const float* __restrict__ pos,
                             float* __restrict__ X)
{
    int i = blockIdx.x * blockDim.x + threadIdx.x;
    if (i >= MM * (CC/4)) return;
    int row = i / (CC/4);
    int c4  = i % (CC/4);
    int t   = idx[row];
    int p   = row & (TT-1);
    float4 a = *(const float4*)(tok + (size_t)t*CC + c4*4);
    float4 e = *(const float4*)(pos + (size_t)p*CC + c4*4);
    a.x += e.x; a.y += e.y; a.z += e.z; a.w += e.w;
    *(float4*)(X + (size_t)row*CC + c4*4) = a;
}

// ---------------------------------------------------------------------------
// LayerNorm: one warp per row; output tf32
// ---------------------------------------------------------------------------
__global__ void ln_kernel(const float* __restrict__ X,
                          const float* __restrict__ g,
                          const float* __restrict__ b,
                          uint32_t* __restrict__ Y)
{
    int row  = blockIdx.x * 8 + (threadIdx.x >> 5);
    int lane = threadIdx.x & 31;
    if (row >= MM) return;
    const float* x = X + (size_t)row*CC;
    float v[12];
    float s = 0.f, ss = 0.f;
#pragma unroll
    for (int i = 0; i < 12; i++) {
        v[i] = x[lane + i*32];
        s  += v[i];
        ss += v[i]*v[i];
    }
#pragma unroll
    for (int o = 16; o; o >>= 1) {
        s  += __shfl_xor_sync(0xFFFFFFFFu, s,  o);
        ss += __shfl_xor_sync(0xFFFFFFFFu, ss, o);
    }
    float mean = s  * (1.0f/CC);
    float var  = ss * (1.0f/CC) - mean*mean;
    float inv  = rsqrtf(var + 1e-5f);
    uint32_t* y = Y + (size_t)row*CC;
#pragma unroll
    for (int i = 0; i < 12; i++) {
        int c = lane + i*32;
        y[c] = f2tf((v[i]-mean)*inv*g[c] + b[c]);
    }
}

// ---------------------------------------------------------------------------
// TF32 GEMM (layer, round-6 proven): 128x128 tile, BK=32, 128 threads,
// warp tile 64x64, 2-stage cp.async double buffer.
// ---------------------------------------------------------------------------
struct GemmSmem {
    uint32_t As[2][128][36];
    uint32_t Bs[2][32][136];
};
#define SMEM_GEMM ((int)sizeof(GemmSmem))   // 71680 bytes

template<bool RELU, bool RES, bool OUTTF>
__device__ __forceinline__
void gemm_core(GemmSmem* sm,
               const uint32_t* __restrict__ A, const uint32_t* __restrict__ B,
               const float* __restrict__ bias, const float* __restrict__ res,
               void* __restrict__ Cv, int M, int N, int K, int bm, int bn)
{
    const int tid  = threadIdx.x;
    const int lane = tid & 31;
    const int wid  = tid >> 5;
    const int wm = (wid & 1) * 64;
    const int wn = (wid >> 1) * 64;
    const int grp = lane >> 2;
    const int tg  = lane & 3;

    float acc[4][8][4];
#pragma unroll
    for (int mt = 0; mt < 4; mt++)
#pragma unroll
        for (int nt = 0; nt < 8; nt++)
#pragma unroll
            for (int e = 0; e < 4; e++) acc[mt][nt][e] = 0.f;

    auto issue = [&](int s, int k0) {
#pragma unroll
        for (int p = 0; p < 8; p++) {
            int i  = tid + p*128;
            int r  = i >> 3;
            int c4 = (i & 7) * 4;
            cp_async16(&sm->As[s][r][c4], A + (size_t)(bm + r)*K + k0 + c4);
        }
#pragma unroll
        for (int p = 0; p < 8; p++) {
            int i  = tid + p*128;
            int r  = i >> 5;
            int c4 = (i & 31) * 4;
            cp_async16(&sm->Bs[s][r][c4], B + (size_t)(k0 + r)*N + bn + c4);
        }
        CP_COMMIT();
    };

    const int nIter = K >> 5;
    issue(0, 0);

    for (int it = 0; it < nIter; it++) {
        const int cur = it & 1;
        CP_WAIT0();
        __syncthreads();
        if (it + 1 < nIter) issue(cur ^ 1, (it + 1) << 5);

#pragma unroll
        for (int kk = 0; kk < 32; kk += 8) {
            uint32_t af[4][4], bf[8][2];
#pragma unroll
            for (int mt = 0; mt < 4; mt++) {
                int r = wm + mt*16 + grp;
                af[mt][0] = sm->As[cur][r    ][kk + tg    ];
                af[mt][1] = sm->As[cur][r + 8][kk + tg    ];
                af[mt][2] = sm->As[cur][r    ][kk + tg + 4];
                af[mt][3] = sm->As[cur][r + 8][kk + tg + 4];
            }
#pragma unroll
            for (int nt = 0; nt < 8; nt++) {
                int c = wn + nt*8 + grp;
                bf[nt][0] = sm->Bs[cur][kk + tg    ][c];
                bf[nt][1] = sm->Bs[cur][kk + tg + 4][c];
            }
#pragma unroll
            for (int mt = 0; mt < 4; mt++)
#pragma unroll
                for (int nt = 0; nt < 8; nt++)
                    mma_tf32(acc[mt][nt], af[mt], bf[nt]);
        }
    }

    // Epilogue
#pragma unroll
    for (int mt = 0; mt < 4; mt++) {
        int r0 = bm + wm + mt*16 + grp;
        int r1 = r0 + 8;
#pragma unroll
        for (int nt = 0; nt < 8; nt++) {
            int c = bn + wn + nt*8 + tg*2;
            float o0x = acc[mt][nt][0], o0y = acc[mt][nt][1];
            float o1x = acc[mt][nt][2], o1y = acc[mt][nt][3];
            if (bias) {
                float bv0 = bias[c], bv1 = bias[c+1];
                o0x += bv0; o0y += bv1; o1x += bv0; o1y += bv1;
            }
            if (RES) {
                float2 ra = *(const float2*)(res + (size_t)r0*N + c);
                float2 rb = *(const float2*)(res + (size_t)r1*N + c);
                o0x += ra.x; o0y += ra.y; o1x += rb.x; o1y += rb.y;
            }
            if (RELU) {
                o0x = fmaxf(o0x, 0.f); o0y = fmaxf(o0y, 0.f);
                o1x = fmaxf(o1x, 0.f); o1y = fmaxf(o1y, 0.f);
            }
            if (OUTTF) {
                uint32_t* C = (uint32_t*)Cv;
                uint2 w0 = {f2tf(o0x), f2tf(o0y)};
                uint2 w1 = {f2tf(o1x), f2tf(o1y)};
                *(uint2*)(C + (size_t)r0*N + c) = w0;
                *(uint2*)(C + (size_t)r1*N + c) = w1;
            } else {
                float* C = (float*)Cv;
                float2 w0 = {o0x, o0y};
                float2 w1 = {o1x, o1y};
                *(float2*)(C + (size_t)r0*N + c) = w0;
                *(float2*)(C + (size_t)r1*N + c) = w1;
            }
        }
    }
}

template<bool RELU, bool RES, bool OUTTF>
__global__ __launch_bounds__(128)
void tgemm(const uint32_t* __restrict__ A, const uint32_t* __restrict__ B,
           const float* __restrict__ bias, const float* __restrict__ res,
           void* __restrict__ C, int M, int N, int K)
{
    extern __shared__ GemmSmem smg[];
    gemm_core<RELU, RES, OUTTF>(smg, A, B, bias, res, C, M, N, K,
                                blockIdx.y * 128, blockIdx.x * 128);
}

// Fused QKV: grid.x = 9 (3 matrices x 3 col-tiles), grid.y = 64. tf32 out.
__global__ __launch_bounds__(128)
void qkv_gemm(const uint32_t* __restrict__ A,
              const uint32_t* __restrict__ Wq, const uint32_t* __restrict__ Wk,
              const uint32_t* __restrict__ Wv,
              uint32_t* __restrict__ Q, uint32_t* __restrict__ Ko, uint32_t* __restrict__ V)
{
    extern __shared__ GemmSmem smg[];
    int sel = blockIdx.x / 3;
    int bn  = (blockIdx.x % 3) * 128;
    const uint32_t* B = (sel == 0) ? Wq : (sel == 1) ? Wk : Wv;
    uint32_t*       C = (sel == 0) ? Q  : (sel == 1) ? Ko : V;
    gemm_core<false, false, true>(smg, A, B, nullptr, nullptr, C,
                                  MM, CC, CC, blockIdx.y * 128, bn);
}

// ---------------------------------------------------------------------------
// Small-M-tile GEMM for the N=384 projection GEMMs (Wo, W2): 64x128 tile,
// BK=32, 128 threads (4 warps of 32x64), 2-stage cp.async, 53 KB smem,
// 4 CTAs/SM (16 warps/SM). Always bias+residual, f32 out.
// Grid: (N/128=3, M/64=128) = 384 blocks vs 192 for the 128-tile version.
// ---------------------------------------------------------------------------
struct GemmSmem64 {
    uint32_t As[2][64][36];
    uint32_t Bs[2][32][136];
};
#define SMEM_GEMM64 ((int)sizeof(GemmSmem64))   // 53248 bytes

__global__ __launch_bounds__(128, 4)
void tgemm64(const uint32_t* __restrict__ A, const uint32_t* __restrict__ B,
             const float* __restrict__ bias, const float* __restrict__ res,
             float* __restrict__ C, int M, int N, int K)
{
    extern __shared__ GemmSmem64 sm64[];
    GemmSmem64* sm = sm64;

    const int bm = blockIdx.y * 64;
    const int bn = blockIdx.x * 128;
    const int tid  = threadIdx.x;
    const int lane = tid & 31;
    const int wid  = tid >> 5;
    const int wm = (wid & 1) * 32;
    const int wn = (wid >> 1) * 64;
    const int grp = lane >> 2;
    const int tg  = lane & 3;

    float acc[2][8][4];
#pragma unroll
    for (int mt = 0; mt < 2; mt++)
#pragma unroll
        for (int nt = 0; nt < 8; nt++)
#pragma unroll
            for (int e = 0; e < 4; e++) acc[mt][nt][e] = 0.f;

    auto issue = [&](int s, int k0) {
#pragma unroll
        for (int p = 0; p < 4; p++) {          // A: 64x32 = 512 float4
            int i  = tid + p*128;
            int r  = i >> 3;
            int c4 = (i & 7) * 4;
            cp_async16(&sm->As[s][r][c4], A + (size_t)(bm + r)*K + k0 + c4);
        }
#pragma unroll
        for (int p = 0; p < 8; p++) {          // B: 32x128 = 1024 float4
            int i  = tid + p*128;
            int r  = i >> 5;
            int c4 = (i & 31) * 4;
            cp_async16(&sm->Bs[s][r][c4], B + (size_t)(k0 + r)*N + bn + c4);
        }
        CP_COMMIT();
    };

    const int nIter = K >> 5;
    issue(0, 0);

    for (int it = 0; it < nIter; it++) {
        const int cur = it & 1;
        CP_WAIT0();
        __syncthreads();
        if (it + 1 < nIter) issue(cur ^ 1, (it + 1) << 5);

#pragma unroll
        for (int kk = 0; kk < 32; kk += 8) {
            uint32_t af[2][4], bf[8][2];
#pragma unroll
            for (int mt = 0; mt < 2; mt++) {
                int r = wm + mt*16 + grp;
                af[mt][0] = sm->As[cur][r    ][kk + tg    ];
                af[mt][1] = sm->As[cur][r + 8][kk + tg    ];
                af[mt][2] = sm->As[cur][r    ][kk + tg + 4];
                af[mt][3] = sm->As[cur][r + 8][kk + tg + 4];
            }
#pragma unroll
            for (int nt = 0; nt < 8; nt++) {
                int c = wn + nt*8 + grp;
                bf[nt][0] = sm->Bs[cur][kk + tg    ][c];
                bf[nt][1] = sm->Bs[cur][kk + tg + 4][c];
            }
#pragma unroll
            for (int mt = 0; mt < 2; mt++)
#pragma unroll
                for (int nt = 0; nt < 8; nt++)
                    mma_tf32(acc[mt][nt], af[mt], bf[nt]);
        }
    }

#pragma unroll
    for (int mt = 0; mt < 2; mt++) {
        int r0 = bm + wm + mt*16 + grp;
        int r1 = r0 + 8;
#pragma unroll
        for (int nt = 0; nt < 8; nt++) {
            int c = bn + wn + nt*8 + tg*2;
            float bv0 = bias[c], bv1 = bias[c+1];
            float2 ra = *(const float2*)(res + (size_t)r0*N + c);
            float2 rb = *(const float2*)(res + (size_t)r1*N + c);
            float2 w0 = {acc[mt][nt][0] + bv0 + ra.x, acc[mt][nt][1] + bv1 + ra.y};
            float2 w1 = {acc[mt][nt][2] + bv0 + rb.x, acc[mt][nt][3] + bv1 + rb.y};
            *(float2*)(C + (size_t)r0*N + c) = w0;
            *(float2*)(C + (size_t)r1*N + c) = w1;
        }
    }
}

// ---------------------------------------------------------------------------
// Tensor-core flash attention; q/k/v tf32, att output tf32.
// ---------------------------------------------------------------------------
#define AKS 68
#define AVS 72
#define APS 36
#define ATT_SMEM ((TT*AKS + TT*AVS + 8*32*APS) * (int)sizeof(uint32_t))

__global__ __launch_bounds__(256, 1)
void attn_mma(const uint32_t* __restrict__ Q, const uint32_t* __restrict__ K,
              const uint32_t* __restrict__ V, uint32_t* __restrict__ O)
{
    extern __shared__ uint32_t sm[];
    uint32_t* Ks = sm;
    uint32_t* Vs = sm + TT*AKS;
    uint32_t* Pb = sm + TT*AKS + TT*AVS;

    const int bh = blockIdx.x;
    const int b  = bh / NH;
    const int h  = bh % NH;
    const float scale = 0.05103103630798288f;  // 1/sqrt(384)

    const int tid = threadIdx.x;
    const uint32_t* kbase = K + (size_t)b*TT*CC + h*HD;
    const uint32_t* vbase = V + (size_t)b*TT*CC + h*HD;

    for (int i = tid; i < TT*16; i += 256) {
        int t  = i >> 4;
        int d4 = (i & 15) * 4;
        *(uint4*)&Ks[t*AKS + d4] = *(const uint4*)(kbase + (size_t)t*CC + d4);
        *(uint4*)&Vs[t*AVS + d4] = *(const uint4*)(vbase + (size_t)t*CC + d4);
    }
    __syncthreads();

    const int lane = tid & 31;
    const int w    = tid >> 5;
    const int grp  = lane >> 2;
    const int tg   = lane & 3;
    const int q0   = w * 32;

    const uint32_t* qbase = Q + (size_t)b*TT*CC + h*HD;
    uint32_t qa[2][8][4];
#pragma unroll
    for (int mt = 0; mt < 2; mt++) {
        int ra = q0 + mt*16 + grp;
        int rb = ra + 8;
#pragma unroll
        for (int ks = 0; ks < 8; ks++) {
            int d = ks*8 + tg;
            qa[mt][ks][0] = qbase[(size_t)ra*CC + d    ];
            qa[mt][ks][1] = qbase[(size_t)rb*CC + d    ];
            qa[mt][ks][2] = qbase[(size_t)ra*CC + d + 4];
            qa[mt][ks][3] = qbase[(size_t)rb*CC + d + 4];
        }
    }

    float o[2][8][4];
#pragma unroll
    for (int mt = 0; mt < 2; mt++)
#pragma unroll
        for (int nt = 0; nt < 8; nt++)
#pragma unroll
            for (int e = 0; e < 4; e++) o[mt][nt][e] = 0.f;

    float mrow[2][2] = {{-1e30f,-1e30f},{-1e30f,-1e30f}};
    float lrow[2][2] = {{0.f,0.f},{0.f,0.f}};

    uint32_t* myP = Pb + w * 32 * APS;

    for (int j = 0; j <= w; j++) {
        const int kbeg = j * 32;
        float s[2][4][4];
#pragma unroll
        for (int mt = 0; mt < 2; mt++)
#pragma unroll
            for (int nt = 0; nt < 4; nt++)
#pragma unroll
                for (int e = 0; e < 4; e++) s[mt][nt][e] = 0.f;

#pragma unroll
        for (int ks = 0; ks < 8; ks++) {
            uint32_t bf[4][2];
#pragma unroll
            for (int nt = 0; nt < 4; nt++) {
                int key = kbeg + nt*8 + grp;
                int d   = ks*8 + tg;
                bf[nt][0] = Ks[key*AKS + d    ];
                bf[nt][1] = Ks[key*AKS + d + 4];
            }
#pragma unroll
            for (int mt = 0; mt < 2; mt++)
#pragma unroll
                for (int nt = 0; nt < 4; nt++)
                    mma_tf32(s[mt][nt], qa[mt][ks], bf[nt]);
        }

#pragma unroll
        for (int mt = 0; mt < 2; mt++) {
            int ra = q0 + mt*16 + grp;
            int rb = ra + 8;
            float rmax0 = -1e30f, rmax1 = -1e30f;
#pragma unroll
            for (int nt = 0; nt < 4; nt++) {
                int c0 = kbeg + nt*8 + 2*tg;
#pragma unroll
                for (int e = 0; e < 4; e++) {
                    float vv = s[mt][nt][e] * scale;
                    int col = c0 + (e & 1);
                    int row = (e < 2) ? ra : rb;
                    if (j == w && col > row) vv = -1e30f;
                    s[mt][nt][e] = vv;
                }
                rmax0 = fmaxf(rmax0, fmaxf(s[mt][nt][0], s[mt][nt][1]));
                rmax1 = fmaxf(rmax1, fmaxf(s[mt][nt][2], s[mt][nt][3]));
            }
            rmax0 = fmaxf(rmax0, __shfl_xor_sync(0xFFFFFFFFu, rmax0, 1));
            rmax0 = fmaxf(rmax0, __shfl_xor_sync(0xFFFFFFFFu, rmax0, 2));
            rmax1 = fmaxf(rmax1, __shfl_xor_sync(0xFFFFFFFFu, rmax1, 1));
            rmax1 = fmaxf(rmax1, __shfl_xor_sync(0xFFFFFFFFu, rmax1, 2));

            float mn0 = fmaxf(mrow[mt][0], rmax0);
            float mn1 = fmaxf(mrow[mt][1], rmax1);
            float cr0 = __expf(mrow[mt][0] - mn0);
            float cr1 = __expf(mrow[mt][1] - mn1);
            mrow[mt][0] = mn0; mrow[mt][1] = mn1;

            float rs0 = 0.f, rs1 = 0.f;
#pragma unroll
            for (int nt = 0; nt < 4; nt++) {
                float p0 = __expf(s[mt][nt][0] - mn0);
                float p1 = __expf(s[mt][nt][1] - mn0);
                float p2 = __expf(s[mt][nt][2] - mn1);
                float p3 = __expf(s[mt][nt][3] - mn1);
                rs0 += p0 + p1; rs1 += p2 + p3;
                int cb = nt*8 + 2*tg;
                myP[(mt*16 + grp    )*APS + cb    ] = f2tf(p0);
                myP[(mt*16 + grp    )*APS + cb + 1] = f2tf(p1);
                myP[(mt*16 + grp + 8)*APS + cb    ] = f2tf(p2);
                myP[(mt*16 + grp + 8)*APS + cb + 1] = f2tf(p3);
            }
            rs0 += __shfl_xor_sync(0xFFFFFFFFu, rs0, 1);
            rs0 += __shfl_xor_sync(0xFFFFFFFFu, rs0, 2);
            rs1 += __shfl_xor_sync(0xFFFFFFFFu, rs1, 1);
            rs1 += __shfl_xor_sync(0xFFFFFFFFu, rs1, 2);
            lrow[mt][0] = lrow[mt][0]*cr0 + rs0;
            lrow[mt][1] = lrow[mt][1]*cr1 + rs1;
#pragma unroll
            for (int nt = 0; nt < 8; nt++) {
                o[mt][nt][0] *= cr0; o[mt][nt][1] *= cr0;
                o[mt][nt][2] *= cr1; o[mt][nt][3] *= cr1;
            }
        }
        __syncwarp();

#pragma unroll
        for (int ks2 = 0; ks2 < 4; ks2++) {
            uint32_t vb[8][2];
#pragma unroll
            for (int nt = 0; nt < 8; nt++) {
                int key = kbeg + ks2*8 + tg;
                int d   = nt*8 + grp;
                vb[nt][0] = Vs[ key     *AVS + d];
                vb[nt][1] = Vs[(key + 4)*AVS + d];
            }
#pragma unroll
            for (int mt = 0; mt < 2; mt++) {
                uint32_t pa[4];
                pa[0] = myP[(mt*16 + grp    )*APS + ks2*8 + tg    ];
                pa[1] = myP[(mt*16 + grp + 8)*APS + ks2*8 + tg    ];
                pa[2] = myP[(mt*16 + grp    )*APS + ks2*8 + tg + 4];
                pa[3] = myP[(mt*16 + grp + 8)*APS + ks2*8 + tg + 4];
#pragma unroll
                for (int nt = 0; nt < 8; nt++)
                    mma_tf32(o[mt][nt], pa, vb[nt]);
            }
        }
        __syncwarp();
    }

    uint32_t* obase = O + (size_t)b*TT*CC + h*HD;
#pragma unroll
    for (int mt = 0; mt < 2; mt++) {
        int ra = q0 + mt*16 + grp;
        int rb = ra + 8;
        float inv0 = 1.f / lrow[mt][0];
        float inv1 = 1.f / lrow[mt][1];
#pragma unroll
        for (int nt = 0; nt < 8; nt++) {
            int d = nt*8 + 2*tg;
            uint2 w0 = {f2tf(o[mt][nt][0]*inv0), f2tf(o[mt][nt][1]*inv0)};
            uint2 w1 = {f2tf(o[mt][nt][2]*inv1), f2tf(o[mt][nt][3]*inv1)};
            *(uint2*)(obase + (size_t)ra*CC + d) = w0;
            *(uint2*)(obase + (size_t)rb*CC + d) = w1;
        }
    }
}

// ---------------------------------------------------------------------------
// Host
// ---------------------------------------------------------------------------
extern "C" void kernel_launch(void* const* d_in, const int* in_sizes, int n_in,
                              void* d_out, int out_size)
{
    (void)in_sizes; (void)n_in; (void)out_size;

    const int*   idx     = (const int*)  d_in[0];
    const float* tok_emb = (const float*)d_in[1];
    const float* pos_emb = (const float*)d_in[2];
    const float* ln1_g   = (const float*)d_in[3];
    const float* ln1_b   = (const float*)d_in[4];
    const float* wq      = (const float*)d_in[5];
    const float* wk      = (const float*)d_in[6];
    const float* wv      = (const float*)d_in[7];
    const float* wo      = (const float*)d_in[8];
    const float* wo_b    = (const float*)d_in[9];
    const float* ln2_g   = (const float*)d_in[10];
    const float* ln2_b   = (const float*)d_in[11];
    const float* w1      = (const float*)d_in[12];
    const float* b1      = (const float*)d_in[13];
    const float* w2      = (const float*)d_in[14];
    const float* b2      = (const float*)d_in[15];
    const float* lnf_g   = (const float*)d_in[16];
    const float* lnf_b   = (const float*)d_in[17];
    const float* lm_w    = (const float*)d_in[18];
    const float* lm_b    = (const float*)d_in[19];
    float* out = (float*)d_out;

    float *x;
    uint32_t *h, *q, *k, *v, *att, *u, *wt;
    cudaGetSymbolAddress((void**)&x,   g_x);
    cudaGetSymbolAddress((void**)&h,   g_h);
    cudaGetSymbolAddress((void**)&q,   g_q);
    cudaGetSymbolAddress((void**)&k,   g_k);
    cudaGetSymbolAddress((void**)&v,   g_v);
    cudaGetSymbolAddress((void**)&att, g_att);
    cudaGetSymbolAddress((void**)&u,   g_u);
    cudaGetSymbolAddress((void**)&wt,  g_wt);

    cudaFuncSetAttribute(attn_mma, cudaFuncAttributeMaxDynamicSharedMemorySize, ATT_SMEM);
    cudaFuncSetAttribute(tgemm<false,false,false>, cudaFuncAttributeMaxDynamicSharedMemorySize, SMEM_GEMM);
    cudaFuncSetAttribute(tgemm<true ,false,true >, cudaFuncAttributeMaxDynamicSharedMemorySize, SMEM_GEMM);
    cudaFuncSetAttribute(qkv_gemm,                 cudaFuncAttributeMaxDynamicSharedMemorySize, SMEM_GEMM);
    cudaFuncSetAttribute(tgemm64,                  cudaFuncAttributeMaxDynamicSharedMemorySize, SMEM_GEMM64);

    // Pre-convert all weights to tf32 (single launch)
    cvt_all_kernel<<<(CVT_N6 + 255)/256, 256>>>(wq, wk, wv, wo, w1, w2, lm_w, wt);

    {
        int total = MM * (CC/4);
        embed_kernel<<<(total + 255)/256, 256>>>(idx, tok_emb, pos_emb, x);
    }

    for (int L = 0; L < LL; L++) {
        const float* g1  = ln1_g + (size_t)L*CC;
        const float* bg1 = ln1_b + (size_t)L*CC;
        const uint32_t* Wq = wt + OFF_WQ + (size_t)L*CC*CC;
        const uint32_t* Wk = wt + OFF_WK + (size_t)L*CC*CC;
        const uint32_t* Wv = wt + OFF_WV + (size_t)L*CC*CC;
        const uint32_t* Wo = wt + OFF_WO + (size_t)L*CC*CC;
        const float* Wob = wo_b + (size_t)L*CC;
        const float* g2  = ln2_g + (size_t)L*CC;
        const float* bg2 = ln2_b + (size_t)L*CC;
        const uint32_t* W1 = wt + OFF_W1 + (size_t)L*CC*FF;
        const float* B1  = b1 + (size_t)L*FF;
        const uint32_t* W2 = wt + OFF_W2 + (size_t)L*FF*CC;
        const float* B2  = b2 + (size_t)L*CC;

        ln_kernel<<<MM/8, 256>>>(x, g1, bg1, h);
        qkv_gemm<<<dim3(9, 64), 128, SMEM_GEMM>>>(h, Wq, Wk, Wv, q, k, v);
        attn_mma<<<BB*NH, 256, ATT_SMEM>>>(q, k, v, att);
        // x += att @ Wo + wo_b   (64-row-tile kernel: 384 blocks, 4 CTAs/SM)
        tgemm64<<<dim3(CC/128, MM/64), 128, SMEM_GEMM64>>>(
            att, Wo, Wob, x, x, MM, CC, CC);
        ln_kernel<<<MM/8, 256>>>(x, g2, bg2, h);
        // u = relu(h @ W1 + b1), tf32 out
        tgemm<true,false,true><<<dim3(FF/128, MM/128), 128, SMEM_GEMM>>>(
            h, W1, B1, nullptr, u, MM, FF, CC);
        // x += u @ W2 + b2       (64-row-tile kernel)
        tgemm64<<<dim3(CC/128, MM/64), 128, SMEM_GEMM64>>>(
            u, W2, B2, x, x, MM, CC, FF);
    }

    ln_kernel<<<MM/8, 256>>>(x, lnf_g, lnf_b, h);
    // logits = h @ lm_w + lm_b  (round-6 proven 128x128 kernel)
    tgemm<false,false,false><<<dim3(VV/128, MM/128), 128, SMEM_GEMM>>>(
        h, wt + OFF_LM, lm_b, nullptr, out, MM, VV, CC);
}

// round 11
// speedup vs baseline: 1.1268x; 1.0018x over previous
#include <cuda_runtime.h>
#include <math.h>
#include <stdint.h>

// Problem dims
#define BB 32
#define TT 256
#define CC 384
#define LL 6
#define NH 6
#define HD 64
#define VV 32000
#define MM (BB*TT)      // 8192
#define FF (4*CC)       // 1536

// tf32 weight scratch layout (element offsets) — stored TRANSPOSED [N][K]
// with k permuted per 8-group: [k,k+4,k+1,k+5,k+2,k+6,k+3,k+7]
#define OFF_WQ 0
#define OFF_WK 884736
#define OFF_WV 1769472
#define OFF_WO 2654208
#define OFF_W1 3538944
#define OFF_W2 7077888
#define OFF_LM 10616832
#define WT_TOTAL 22904832

// Scratch (device globals; no allocations allowed)
__device__ float    g_x[MM*CC];          // residual stream (f32)
__device__ uint32_t g_h[MM*CC];          // LN output (tf32)
__device__ uint32_t g_q[MM*CC];
__device__ uint32_t g_k[MM*CC];
__device__ uint32_t g_v[MM*CC];
__device__ uint32_t g_att[MM*CC];
__device__ uint32_t g_u[MM*FF];
__device__ uint32_t g_wt[WT_TOTAL];      // tf32 transposed weights

// ---------------------------------------------------------------------------
// Helpers
// ---------------------------------------------------------------------------
__device__ __forceinline__ uint32_t f2tf(float f) {
    uint32_t u;
    asm("cvt.rna.tf32.f32 %0, %1;" : "=r"(u) : "f"(f));
    return u;
}

__device__ __forceinline__ void mma_tf32(float* c, const uint32_t* a, const uint32_t* b) {
    asm volatile(
        "mma.sync.aligned.m16n8k8.row.col.f32.tf32.tf32.f32 "
        "{%0,%1,%2,%3}, {%4,%5,%6,%7}, {%8,%9}, {%0,%1,%2,%3};"
        : "+f"(c[0]), "+f"(c[1]), "+f"(c[2]), "+f"(c[3])
        : "r"(a[0]), "r"(a[1]), "r"(a[2]), "r"(a[3]),
          "r"(b[0]), "r"(b[1]));
}

__device__ __forceinline__ void cp_async16(void* sptr, const void* gptr) {
    uint32_t sa = (uint32_t)__cvta_generic_to_shared(sptr);
    asm volatile("cp.async.cg.shared.global [%0], [%1], 16;\n" :: "r"(sa), "l"(gptr));
}
#define CP_COMMIT() asm volatile("cp.async.commit_group;\n" ::: "memory")
#define CP_WAIT0()  asm volatile("cp.async.wait_group 0;\n" ::: "memory")

// ---------------------------------------------------------------------------
// Fused transpose + tf32 convert of ALL weights, one launch.
// src: [K][N] f32 row-major.  dst: [N][K] tf32 with per-8-group k permutation
// stored[g+2t] = orig[g+t], stored[g+2t+1] = orig[g+t+4]  (t = 0..3).
// ---------------------------------------------------------------------------
#define R0 110592
#define R1 221184
#define R2 331776
#define R3 442368
#define R4 884736                  // +w1: LL*(CC/8)*FF = 442368
#define R5 1327104                 // +w2: LL*(FF/8)*CC = 442368
#define R6 2863104                 // +lm: (CC/8)*VV    = 1536000

__global__ void cvt_trans_kernel(const float* __restrict__ wq, const float* __restrict__ wk,
                                 const float* __restrict__ wv, const float* __restrict__ wo,
                                 const float* __restrict__ w1, const float* __restrict__ w2,
                                 const float* __restrict__ lm, uint32_t* __restrict__ wt)
{
    int f = blockIdx.x * blockDim.x + threadIdx.x;
    if (f >= R6) return;
    const float* src; uint32_t* dst; int K, N, local;
    if (f < R0)      { src = wq; dst = wt + OFF_WQ; K = CC; N = CC; local = f; }
    else if (f < R1) { src = wk; dst = wt + OFF_WK; K = CC; N = CC; local = f - R0; }
    else if (f < R2) { src = wv; dst = wt + OFF_WV; K = CC; N = CC; local = f - R1; }
    else if (f < R3) { src = wo; dst = wt + OFF_WO; K = CC; N = CC; local = f - R2; }
    else if (f < R4) { src = w1; dst = wt + OFF_W1; K = CC; N = FF; local = f - R3; }
    else if (f < R5) { src = w2; dst = wt + OFF_W2; K = FF; N = CC; local = f - R4; }
    else             { src = lm; dst = wt + OFF_LM; K = CC; N = VV; local = f - R5; }

    int PL    = (K >> 3) * N;          // groups per layer
    int layer = local / PL;
    int r     = local - layer * PL;
    int kg    = r / N;
    int n     = r - kg * N;

    const float* s0 = src + (size_t)layer*K*N + (size_t)(kg*8)*N + n;
    uint32_t o[8];
#pragma unroll
    for (int t = 0; t < 4; t++) {
        o[2*t]   = f2tf(s0[(size_t)t*N]);
        o[2*t+1] = f2tf(s0[(size_t)(t+4)*N]);
    }
    uint32_t* d = dst + (size_t)layer*K*N + (size_t)n*K + kg*8;
    *(uint4*)(d)     = make_uint4(o[0], o[1], o[2], o[3]);
    *(uint4*)(d + 4) = make_uint4(o[4], o[5], o[6], o[7]);
}

// ---------------------------------------------------------------------------
// Embedding (f32 residual stream)
// ---------------------------------------------------------------------------
__global__ void embed_kernel(const int* __restrict__ idx,
                             const float* __restrict__ tok,
                             const float* __restrict__ pos,
                             float* __restrict__ X)
{
    int i = blockIdx.x * blockDim.x + threadIdx.x;
    if (i >= MM * (CC/4)) return;
    int row = i / (CC/4);
    int c4  = i % (CC/4);
    int t   = idx[row];
    int p   = row & (TT-1);
    float4 a = *(const float4*)(tok + (size_t)t*CC + c4*4);
    float4 e = *(const float4*)(pos + (size_t)p*CC + c4*4);
    a.x += e.x; a.y += e.y; a.z += e.z; a.w += e.w;
    *(float4*)(X + (size_t)row*CC + c4*4) = a;
}

// ---------------------------------------------------------------------------
// LayerNorm: one warp per row; output tf32
// ---------------------------------------------------------------------------
__global__ void ln_kernel(const float* __restrict__ X,
                          const float* __restrict__ g,
                          const float* __restrict__ b,
                          uint32_t* __restrict__ Y)
{
    int row  = blockIdx.x * 8 + (threadIdx.x >> 5);
    int lane = threadIdx.x & 31;
    if (row >= MM) return;
    const float* x = X + (size_t)row*CC;
    float v[12];
    float s = 0.f, ss = 0.f;
#pragma unroll
    for (int i = 0; i < 12; i++) {
        v[i] = x[lane + i*32];
        s  += v[i];
        ss += v[i]*v[i];
    }
#pragma unroll
    for (int o = 16; o; o >>= 1) {
        s  += __shfl_xor_sync(0xFFFFFFFFu, s,  o);
        ss += __shfl_xor_sync(0xFFFFFFFFu, ss, o);
    }
    float mean = s  * (1.0f/CC);
    float var  = ss * (1.0f/CC) - mean*mean;
    float inv  = rsqrtf(var + 1e-5f);
    uint32_t* y = Y + (size_t)row*CC;
#pragma unroll
    for (int i = 0; i < 12; i++) {
        int c = lane + i*32;
        y[c] = f2tf((v[i]-mean)*inv*g[c] + b[c]);
    }
}

// ---------------------------------------------------------------------------
// TF32 GEMM: 128x128 tile, BK=32, 128 threads, warp tile 64x64, 2-stage
// cp.async. B transposed [N][K] k-permuted in gmem -> n-major smem tile,
// B fragments via single LDS.64 (stride 40 -> 160B rows, 16B-aligned,
// conflict-free: 64-bit bank = (20*grp + tg) mod 32, distinct per phase).
// ---------------------------------------------------------------------------
struct GemmSmem {
    uint32_t As[2][128][36];   // 36864 B
    uint32_t Bs[2][128][40];   // 40960 B (n-major, 32 k + pad)
};
#define SMEM_GEMM ((int)sizeof(GemmSmem))   // 77824 bytes -> 2 CTAs/SM

template<bool RELU, bool RES, bool OUTTF>
__device__ __forceinline__
void gemm_core(GemmSmem* sm,
               const uint32_t* __restrict__ A, const uint32_t* __restrict__ B,
               const float* __restrict__ bias, const float* __restrict__ res,
               void* __restrict__ Cv, int M, int N, int K, int bm, int bn)
{
    const int tid  = threadIdx.x;
    const int lane = tid & 31;
    const int wid  = tid >> 5;
    const int wm = (wid & 1) * 64;
    const int wn = (wid >> 1) * 64;
    const int grp = lane >> 2;
    const int tg  = lane & 3;

    float acc[4][8][4];
#pragma unroll
    for (int mt = 0; mt < 4; mt++)
#pragma unroll
        for (int nt = 0; nt < 8; nt++)
#pragma unroll
            for (int e = 0; e < 4; e++) acc[mt][nt][e] = 0.f;

    auto issue = [&](int s, int k0) {
#pragma unroll
        for (int p = 0; p < 8; p++) {
            int i  = tid + p*128;
            int r  = i >> 3;
            int c4 = (i & 7) * 4;
            cp_async16(&sm->As[s][r][c4], A + (size_t)(bm + r)*K + k0 + c4);
        }
#pragma unroll
        for (int p = 0; p < 8; p++) {
            int i  = tid + p*128;
            int r  = i >> 3;              // n-local row 0..127
            int c4 = (i & 7) * 4;         // k chunk 0..28
            cp_async16(&sm->Bs[s][r][c4], B + (size_t)(bn + r)*K + k0 + c4);
        }
        CP_COMMIT();
    };

    const int nIter = K >> 5;
    issue(0, 0);

    for (int it = 0; it < nIter; it++) {
        const int cur = it & 1;
        CP_WAIT0();
        __syncthreads();
        if (it + 1 < nIter) issue(cur ^ 1, (it + 1) << 5);

#pragma unroll
        for (int kk = 0; kk < 32; kk += 8) {
            uint32_t af[4][4], bf[8][2];
#pragma unroll
            for (int mt = 0; mt < 4; mt++) {
                int r = wm + mt*16 + grp;
                af[mt][0] = sm->As[cur][r    ][kk + tg    ];
                af[mt][1] = sm->As[cur][r + 8][kk + tg    ];
                af[mt][2] = sm->As[cur][r    ][kk + tg + 4];
                af[mt][3] = sm->As[cur][r + 8][kk + tg + 4];
            }
#pragma unroll
            for (int nt = 0; nt < 8; nt++) {
                int c = wn + nt*8 + grp;
                uint2 bb = *(const uint2*)&sm->Bs[cur][c][kk + 2*tg];
                bf[nt][0] = bb.x;
                bf[nt][1] = bb.y;
            }
#pragma unroll
            for (int mt = 0; mt < 4; mt++)
#pragma unroll
                for (int nt = 0; nt < 8; nt++)
                    mma_tf32(acc[mt][nt], af[mt], bf[nt]);
        }
    }

    // Epilogue
#pragma unroll
    for (int mt = 0; mt < 4; mt++) {
        int r0 = bm + wm + mt*16 + grp;
        int r1 = r0 + 8;
#pragma unroll
        for (int nt = 0; nt < 8; nt++) {
            int c = bn + wn + nt*8 + tg*2;
            float o0x = acc[mt][nt][0], o0y = acc[mt][nt][1];
            float o1x = acc[mt][nt][2], o1y = acc[mt][nt][3];
            if (bias) {
                float bv0 = bias[c], bv1 = bias[c+1];
                o0x += bv0; o0y += bv1; o1x += bv0; o1y += bv1;
            }
            if (RES) {
                float2 ra = *(const float2*)(res + (size_t)r0*N + c);
                float2 rb = *(const float2*)(res + (size_t)r1*N + c);
                o0x += ra.x; o0y += ra.y; o1x += rb.x; o1y += rb.y;
            }
            if (RELU) {
                o0x = fmaxf(o0x, 0.f); o0y = fmaxf(o0y, 0.f);
                o1x = fmaxf(o1x, 0.f); o1y = fmaxf(o1y, 0.f);
            }
            if (OUTTF) {
                uint32_t* C = (uint32_t*)Cv;
                uint2 w0 = {f2tf(o0x), f2tf(o0y)};
                uint2 w1 = {f2tf(o1x), f2tf(o1y)};
                *(uint2*)(C + (size_t)r0*N + c) = w0;
                *(uint2*)(C + (size_t)r1*N + c) = w1;
            } else {
                float* C = (float*)Cv;
                float2 w0 = {o0x, o0y};
                float2 w1 = {o1x, o1y};
                *(float2*)(C + (size_t)r0*N + c) = w0;
                *(float2*)(C + (size_t)r1*N + c) = w1;
            }
        }
    }
}

template<bool RELU, bool RES, bool OUTTF>
__global__ __launch_bounds__(128)
void tgemm(const uint32_t* __restrict__ A, const uint32_t* __restrict__ B,
           const float* __restrict__ bias, const float* __restrict__ res,
           void* __restrict__ C, int M, int N, int K)
{
    extern __shared__ GemmSmem smg[];
    gemm_core<RELU, RES, OUTTF>(smg, A, B, bias, res, C, M, N, K,
                                blockIdx.y * 128, blockIdx.x * 128);
}

// Fused QKV: grid.x = 9 (3 matrices x 3 col-tiles), grid.y = 64. tf32 out.
__global__ __launch_bounds__(128)
void qkv_gemm(const uint32_t* __restrict__ A,
              const uint32_t* __restrict__ Wq, const uint32_t* __restrict__ Wk,
              const uint32_t* __restrict__ Wv,
              uint32_t* __restrict__ Q, uint32_t* __restrict__ Ko, uint32_t* __restrict__ V)
{
    extern __shared__ GemmSmem smg[];
    int sel = blockIdx.x / 3;
    int bn  = (blockIdx.x % 3) * 128;
    const uint32_t* B = (sel == 0) ? Wq : (sel == 1) ? Wk : Wv;
    uint32_t*       C = (sel == 0) ? Q  : (sel == 1) ? Ko : V;
    gemm_core<false, false, true>(smg, A, B, nullptr, nullptr, C,
                                  MM, CC, CC, blockIdx.y * 128, bn);
}

// ---------------------------------------------------------------------------
// Small-M-tile GEMM for the N=384 projections (Wo, W2): 64x128 tile, BK=32,
// 128 threads (4 warps of 32x64), 2-stage cp.async, transposed B.
// Bs stride 36 (144B rows = 9*16 -> cp.async 16B-aligned; 64-bit bank =
// (18*grp + tg) mod 32, distinct within each 16-lane phase -> conflict-free).
// smem 55296 B -> 4 CTAs/SM. Always bias+residual, f32 out.
// ---------------------------------------------------------------------------
struct GemmSmem64 {
    uint32_t As[2][64][36];    // 18432 B
    uint32_t Bs[2][128][36];   // 36864 B
};
#define SMEM_GEMM64 ((int)sizeof(GemmSmem64))   // 55296 bytes

__global__ __launch_bounds__(128, 4)
void tgemm64(const uint32_t* __restrict__ A, const uint32_t* __restrict__ B,
             const float* __restrict__ bias, const float* __restrict__ res,
             float* __restrict__ C, int M, int N, int K)
{
    extern __shared__ GemmSmem64 sm64[];
    GemmSmem64* sm = sm64;

    const int bm = blockIdx.y * 64;
    const int bn = blockIdx.x * 128;
    const int tid  = threadIdx.x;
    const int lane = tid & 31;
    const int wid  = tid >> 5;
    const int wm = (wid & 1) * 32;
    const int wn = (wid >> 1) * 64;
    const int grp = lane >> 2;
    const int tg  = lane & 3;

    float acc[2][8][4];
#pragma unroll
    for (int mt = 0; mt < 2; mt++)
#pragma unroll
        for (int nt = 0; nt < 8; nt++)
#pragma unroll
            for (int e = 0; e < 4; e++) acc[mt][nt][e] = 0.f;

    auto issue = [&](int s, int k0) {
#pragma unroll
        for (int p = 0; p < 4; p++) {          // A: 64x32 = 512 float4
            int i  = tid + p*128;
            int r  = i >> 3;
            int c4 = (i & 7) * 4;
            cp_async16(&sm->As[s][r][c4], A + (size_t)(bm + r)*K + k0 + c4);
        }
#pragma unroll
        for (int p = 0; p < 8; p++) {          // B: 128 n-rows x 32 k = 1024 chunks
            int i  = tid + p*128;
            int r  = i >> 3;
            int c4 = (i & 7) * 4;
            cp_async16(&sm->Bs[s][r][c4], B + (size_t)(bn + r)*K + k0 + c4);
        }
        CP_COMMIT();
    };

    const int nIter = K >> 5;
    issue(0, 0);

    for (int it = 0; it < nIter; it++) {
        const int cur = it & 1;
        CP_WAIT0();
        __syncthreads();
        if (it + 1 < nIter) issue(cur ^ 1, (it + 1) << 5);

#pragma unroll
        for (int kk = 0; kk < 32; kk += 8) {
            uint32_t af[2][4], bf[8][2];
#pragma unroll
            for (int mt = 0; mt < 2; mt++) {
                int r = wm + mt*16 + grp;
                af[mt][0] = sm->As[cur][r    ][kk + tg    ];
                af[mt][1] = sm->As[cur][r + 8][kk + tg    ];
                af[mt][2] = sm->As[cur][r    ][kk + tg + 4];
                af[mt][3] = sm->As[cur][r + 8][kk + tg + 4];
            }
#pragma unroll
            for (int nt = 0; nt < 8; nt++) {
                int c = wn + nt*8 + grp;
                uint2 bb = *(const uint2*)&sm->Bs[cur][c][kk + 2*tg];
                bf[nt][0] = bb.x;
                bf[nt][1] = bb.y;
            }
#pragma unroll
            for (int mt = 0; mt < 2; mt++)
#pragma unroll
                for (int nt = 0; nt < 8; nt++)
                    mma_tf32(acc[mt][nt], af[mt], bf[nt]);
        }
    }

#pragma unroll
    for (int mt = 0; mt < 2; mt++) {
        int r0 = bm + wm + mt*16 + grp;
        int r1 = r0 + 8;
#pragma unroll
        for (int nt = 0; nt < 8; nt++) {
            int c = bn + wn + nt*8 + tg*2;
            float bv0 = bias[c], bv1 = bias[c+1];
            float2 ra = *(const float2*)(res + (size_t)r0*N + c);
            float2 rb = *(const float2*)(res + (size_t)r1*N + c);
            float2 w0 = {acc[mt][nt][0] + bv0 + ra.x, acc[mt][nt][1] + bv1 + ra.y};
            float2 w1 = {acc[mt][nt][2] + bv0 + rb.x, acc[mt][nt][3] + bv1 + rb.y};
            *(float2*)(C + (size_t)r0*N + c) = w0;
            *(float2*)(C + (size_t)r1*N + c) = w1;
        }
    }
}

// ---------------------------------------------------------------------------
// Tensor-core flash attention; q/k/v tf32, att output tf32. (unchanged)
// ---------------------------------------------------------------------------
#define AKS 68
#define AVS 72
#define APS 36
#define ATT_SMEM ((TT*AKS + TT*AVS + 8*32*APS) * (int)sizeof(uint32_t))

__global__ __launch_bounds__(256, 1)
void attn_mma(const uint32_t* __restrict__ Q, const uint32_t* __restrict__ K,
              const uint32_t* __restrict__ V, uint32_t* __restrict__ O)
{
    extern __shared__ uint32_t sm[];
    uint32_t* Ks = sm;
    uint32_t* Vs = sm + TT*AKS;
    uint32_t* Pb = sm + TT*AKS + TT*AVS;

    const int bh = blockIdx.x;
    const int b  = bh / NH;
    const int h  = bh % NH;
    const float scale = 0.05103103630798288f;  // 1/sqrt(384)

    const int tid = threadIdx.x;
    const uint32_t* kbase = K + (size_t)b*TT*CC + h*HD;
    const uint32_t* vbase = V + (size_t)b*TT*CC + h*HD;

    for (int i = tid; i < TT*16; i += 256) {
        int t  = i >> 4;
        int d4 = (i & 15) * 4;
        *(uint4*)&Ks[t*AKS + d4] = *(const uint4*)(kbase + (size_t)t*CC + d4);
        *(uint4*)&Vs[t*AVS + d4] = *(const uint4*)(vbase + (size_t)t*CC + d4);
    }
    __syncthreads();

    const int lane = tid & 31;
    const int w    = tid >> 5;
    const int grp  = lane >> 2;
    const int tg   = lane & 3;
    const int q0   = w * 32;

    const uint32_t* qbase = Q + (size_t)b*TT*CC + h*HD;
    uint32_t qa[2][8][4];
#pragma unroll
    for (int mt = 0; mt < 2; mt++) {
        int ra = q0 + mt*16 + grp;
        int rb = ra + 8;
#pragma unroll
        for (int ks = 0; ks < 8; ks++) {
            int d = ks*8 + tg;
            qa[mt][ks][0] = qbase[(size_t)ra*CC + d    ];
            qa[mt][ks][1] = qbase[(size_t)rb*CC + d    ];
            qa[mt][ks][2] = qbase[(size_t)ra*CC + d + 4];
            qa[mt][ks][3] = qbase[(size_t)rb*CC + d + 4];
        }
    }

    float o[2][8][4];
#pragma unroll
    for (int mt = 0; mt < 2; mt++)
#pragma unroll
        for (int nt = 0; nt < 8; nt++)
#pragma unroll
            for (int e = 0; e < 4; e++) o[mt][nt][e] = 0.f;

    float mrow[2][2] = {{-1e30f,-1e30f},{-1e30f,-1e30f}};
    float lrow[2][2] = {{0.f,0.f},{0.f,0.f}};

    uint32_t* myP = Pb + w * 32 * APS;

    for (int j = 0; j <= w; j++) {
        const int kbeg = j * 32;
        float s[2][4][4];
#pragma unroll
        for (int mt = 0; mt < 2; mt++)
#pragma unroll
            for (int nt = 0; nt < 4; nt++)
#pragma unroll
                for (int e = 0; e < 4; e++) s[mt][nt][e] = 0.f;

#pragma unroll
        for (int ks = 0; ks < 8; ks++) {
            uint32_t bf[4][2];
#pragma unroll
            for (int nt = 0; nt < 4; nt++) {
                int key = kbeg + nt*8 + grp;
                int d   = ks*8 + tg;
                bf[nt][0] = Ks[key*AKS + d    ];
                bf[nt][1] = Ks[key*AKS + d + 4];
            }
#pragma unroll
            for (int mt = 0; mt < 2; mt++)
#pragma unroll
                for (int nt = 0; nt < 4; nt++)
                    mma_tf32(s[mt][nt], qa[mt][ks], bf[nt]);
        }

#pragma unroll
        for (int mt = 0; mt < 2; mt++) {
            int ra = q0 + mt*16 + grp;
            int rb = ra + 8;
            float rmax0 = -1e30f, rmax1 = -1e30f;
#pragma unroll
            for (int nt = 0; nt < 4; nt++) {
                int c0 = kbeg + nt*8 + 2*tg;
#pragma unroll
                for (int e = 0; e < 4; e++) {
                    float vv = s[mt][nt][e] * scale;
                    int col = c0 + (e & 1);
                    int row = (e < 2) ? ra : rb;
                    if (j == w && col > row) vv = -1e30f;
                    s[mt][nt][e] = vv;
                }
                rmax0 = fmaxf(rmax0, fmaxf(s[mt][nt][0], s[mt][nt][1]));
                rmax1 = fmaxf(rmax1, fmaxf(s[mt][nt][2], s[mt][nt][3]));
            }
            rmax0 = fmaxf(rmax0, __shfl_xor_sync(0xFFFFFFFFu, rmax0, 1));
            rmax0 = fmaxf(rmax0, __shfl_xor_sync(0xFFFFFFFFu, rmax0, 2));
            rmax1 = fmaxf(rmax1, __shfl_xor_sync(0xFFFFFFFFu, rmax1, 1));
            rmax1 = fmaxf(rmax1, __shfl_xor_sync(0xFFFFFFFFu, rmax1, 2));

            float mn0 = fmaxf(mrow[mt][0], rmax0);
            float mn1 = fmaxf(mrow[mt][1], rmax1);
            float cr0 = __expf(mrow[mt][0] - mn0);
            float cr1 = __expf(mrow[mt][1] - mn1);
            mrow[mt][0] = mn0; mrow[mt][1] = mn1;

            float rs0 = 0.f, rs1 = 0.f;
#pragma unroll
            for (int nt = 0; nt < 4; nt++) {
                float p0 = __expf(s[mt][nt][0] - mn0);
                float p1 = __expf(s[mt][nt][1] - mn0);
                float p2 = __expf(s[mt][nt][2] - mn1);
                float p3 = __expf(s[mt][nt][3] - mn1);
                rs0 += p0 + p1; rs1 += p2 + p3;
                int cb = nt*8 + 2*tg;
                myP[(mt*16 + grp    )*APS + cb    ] = f2tf(p0);
                myP[(mt*16 + grp    )*APS + cb + 1] = f2tf(p1);
                myP[(mt*16 + grp + 8)*APS + cb    ] = f2tf(p2);
                myP[(mt*16 + grp + 8)*APS + cb + 1] = f2tf(p3);
            }
            rs0 += __shfl_xor_sync(0xFFFFFFFFu, rs0, 1);
            rs0 += __shfl_xor_sync(0xFFFFFFFFu, rs0, 2);
            rs1 += __shfl_xor_sync(0xFFFFFFFFu, rs1, 1);
            rs1 += __shfl_xor_sync(0xFFFFFFFFu, rs1, 2);
            lrow[mt][0] = lrow[mt][0]*cr0 + rs0;
            lrow[mt][1] = lrow[mt][1]*cr1 + rs1;
#pragma unroll
            for (int nt = 0; nt < 8; nt++) {
                o[mt][nt][0] *= cr0; o[mt][nt][1] *= cr0;
                o[mt][nt][2] *= cr1; o[mt][nt][3] *= cr1;
            }
        }
        __syncwarp();

#pragma unroll
        for (int ks2 = 0; ks2 < 4; ks2++) {
            uint32_t vb[8][2];
#pragma unroll
            for (int nt = 0; nt < 8; nt++) {
                int key = kbeg + ks2*8 + tg;
                int d   = nt*8 + grp;
                vb[nt][0] = Vs[ key     *AVS + d];
                vb[nt][1] = Vs[(key + 4)*AVS + d];
            }
#pragma unroll
            for (int mt = 0; mt < 2; mt++) {
                uint32_t pa[4];
                pa[0] = myP[(mt*16 + grp    )*APS + ks2*8 + tg    ];
                pa[1] = myP[(mt*16 + grp + 8)*APS + ks2*8 + tg    ];
                pa[2] = myP[(mt*16 + grp    )*APS + ks2*8 + tg + 4];
                pa[3] = myP[(mt*16 + grp + 8)*APS + ks2*8 + tg + 4];
#pragma unroll
                for (int nt = 0; nt < 8; nt++)
                    mma_tf32(o[mt][nt], pa, vb[nt]);
            }
        }
        __syncwarp();
    }

    uint32_t* obase = O + (size_t)b*TT*CC + h*HD;
#pragma unroll
    for (int mt = 0; mt < 2; mt++) {
        int ra = q0 + mt*16 + grp;
        int rb = ra + 8;
        float inv0 = 1.f / lrow[mt][0];
        float inv1 = 1.f / lrow[mt][1];
#pragma unroll
        for (int nt = 0; nt < 8; nt++) {
            int d = nt*8 + 2*tg;
            uint2 w0 = {f2tf(o[mt][nt][0]*inv0), f2tf(o[mt][nt][1]*inv0)};
            uint2 w1 = {f2tf(o[mt][nt][2]*inv1), f2tf(o[mt][nt][3]*inv1)};
            *(uint2*)(obase + (size_t)ra*CC + d) = w0;
            *(uint2*)(obase + (size_t)rb*CC + d) = w1;
        }
    }
}

// ---------------------------------------------------------------------------
// Host
// ---------------------------------------------------------------------------
extern "C" void kernel_launch(void* const* d_in, const int* in_sizes, int n_in,
                              void* d_out, int out_size)
{
    (void)in_sizes; (void)n_in; (void)out_size;

    const int*   idx     = (const int*)  d_in[0];
    const float* tok_emb = (const float*)d_in[1];
    const float* pos_emb = (const float*)d_in[2];
    const float* ln1_g   = (const float*)d_in[3];
    const float* ln1_b   = (const float*)d_in[4];
    const float* wq      = (const float*)d_in[5];
    const float* wk      = (const float*)d_in[6];
    const float* wv      = (const float*)d_in[7];
    const float* wo      = (const float*)d_in[8];
    const float* wo_b    = (const float*)d_in[9];
    const float* ln2_g   = (const float*)d_in[10];
    const float* ln2_b   = (const float*)d_in[11];
    const float* w1      = (const float*)d_in[12];
    const float* b1      = (const float*)d_in[13];
    const float* w2      = (const float*)d_in[14];
    const float* b2      = (const float*)d_in[15];
    const float* lnf_g   = (const float*)d_in[16];
    const float* lnf_b   = (const float*)d_in[17];
    const float* lm_w    = (const float*)d_in[18];
    const float* lm_b    = (const float*)d_in[19];
    float* out = (float*)d_out;

    float *x;
    uint32_t *h, *q, *k, *v, *att, *u, *wt;
    cudaGetSymbolAddress((void**)&x,   g_x);
    cudaGetSymbolAddress((void**)&h,   g_h);
    cudaGetSymbolAddress((void**)&q,   g_q);
    cudaGetSymbolAddress((void**)&k,   g_k);
    cudaGetSymbolAddress((void**)&v,   g_v);
    cudaGetSymbolAddress((void**)&att, g_att);
    cudaGetSymbolAddress((void**)&u,   g_u);
    cudaGetSymbolAddress((void**)&wt,  g_wt);

    cudaFuncSetAttribute(attn_mma, cudaFuncAttributeMaxDynamicSharedMemorySize, ATT_SMEM);
    cudaFuncSetAttribute(tgemm<false,false,false>, cudaFuncAttributeMaxDynamicSharedMemorySize, SMEM_GEMM);
    cudaFuncSetAttribute(tgemm<true ,false,true >, cudaFuncAttributeMaxDynamicSharedMemorySize, SMEM_GEMM);
    cudaFuncSetAttribute(qkv_gemm,                 cudaFuncAttributeMaxDynamicSharedMemorySize, SMEM_GEMM);
    cudaFuncSetAttribute(tgemm64,                  cudaFuncAttributeMaxDynamicSharedMemorySize, SMEM_GEMM64);

    // Pre-convert + transpose all weights to tf32 [N][K] k-permuted (single launch)
    cvt_trans_kernel<<<(R6 + 255)/256, 256>>>(wq, wk, wv, wo, w1, w2, lm_w, wt);

    {
        int total = MM * (CC/4);
        embed_kernel<<<(total + 255)/256, 256>>>(idx, tok_emb, pos_emb, x);
    }

    for (int L = 0; L < LL; L++) {
        const float* g1  = ln1_g + (size_t)L*CC;
        const float* bg1 = ln1_b + (size_t)L*CC;
        const uint32_t* Wq = wt + OFF_WQ + (size_t)L*CC*CC;
        const uint32_t* Wk = wt + OFF_WK + (size_t)L*CC*CC;
        const uint32_t* Wv = wt + OFF_WV + (size_t)L*CC*CC;
        const uint32_t* Wo = wt + OFF_WO + (size_t)L*CC*CC;
        const float* Wob = wo_b + (size_t)L*CC;
        const float* g2  = ln2_g + (size_t)L*CC;
        const float* bg2 = ln2_b + (size_t)L*CC;
        const uint32_t* W1 = wt + OFF_W1 + (size_t)L*CC*FF;
        const float* B1  = b1 + (size_t)L*FF;
        const uint32_t* W2 = wt + OFF_W2 + (size_t)L*FF*CC;
        const float* B2  = b2 + (size_t)L*CC;

        ln_kernel<<<MM/8, 256>>>(x, g1, bg1, h);
        qkv_gemm<<<dim3(9, 64), 128, SMEM_GEMM>>>(h, Wq, Wk, Wv, q, k, v);
        attn_mma<<<BB*NH, 256, ATT_SMEM>>>(q, k, v, att);
        // x += att @ Wo + wo_b
        tgemm64<<<dim3(CC/128, MM/64), 128, SMEM_GEMM64>>>(
            att, Wo, Wob, x, x, MM, CC, CC);
        ln_kernel<<<MM/8, 256>>>(x, g2, bg2, h);
        // u = relu(h @ W1 + b1), tf32 out
        tgemm<true,false,true><<<dim3(FF/128, MM/128), 128, SMEM_GEMM>>>(
            h, W1, B1, nullptr, u, MM, FF, CC);
        // x += u @ W2 + b2
        tgemm64<<<dim3(CC/128, MM/64), 128, SMEM_GEMM64>>>(
            u, W2, B2, x, x, MM, CC, FF);
    }

    ln_kernel<<<MM/8, 256>>>(x, lnf_g, lnf_b, h);
    // logits = h @ lm_w + lm_b
    tgemm<false,false,false><<<dim3(VV/128, MM/128), 128, SMEM_GEMM>>>(
        h, wt + OFF_LM, lm_b, nullptr, out, MM, VV, CC);
}

// round 12
// speedup vs baseline: 1.6103x; 1.4291x over previous
#include <cuda_runtime.h>
#include <cuda_fp16.h>
#include <math.h>
#include <stdint.h>

// Problem dims
#define BB 32
#define TT 256
#define CC 384
#define LL 6
#define NH 6
#define HD 64
#define VV 32000
#define MM (BB*TT)      // 8192
#define FF (4*CC)       // 1536

// fp16 weight scratch layout (uint32 = half2 units), stored TRANSPOSED [N][Kp]
#define OFF16_WQ 0
#define OFF16_WK 442368
#define OFF16_WV 884736
#define OFF16_WO 1327104
#define OFF16_W1 1769472
#define OFF16_W2 3538944
#define OFF16_LM 5308416
#define WT16_TOTAL 11452416

// Scratch (device globals; no allocations allowed)
__device__ float    g_x[MM*CC];          // residual stream (f32)
__device__ uint32_t g_h[MM*CC/2];        // LN output (fp16 packed, Kp=192)
__device__ uint32_t g_q[MM*CC];          // tf32 (attention input)
__device__ uint32_t g_k[MM*CC];
__device__ uint32_t g_v[MM*CC];
__device__ uint32_t g_att[MM*CC/2];      // fp16 packed
__device__ uint32_t g_u[MM*FF/2];        // fp16 packed
__device__ uint32_t g_wt[WT16_TOTAL];    // fp16 transposed weights

// ---------------------------------------------------------------------------
// Helpers
// ---------------------------------------------------------------------------
__device__ __forceinline__ uint32_t f2tf(float f) {
    uint32_t u;
    asm("cvt.rna.tf32.f32 %0, %1;" : "=r"(u) : "f"(f));
    return u;
}

__device__ __forceinline__ uint32_t packh2(float lo, float hi) {
    __half2 h = __floats2half2_rn(lo, hi);
    return *(uint32_t*)&h;
}

__device__ __forceinline__ void mma_tf32(float* c, const uint32_t* a, const uint32_t* b) {
    asm volatile(
        "mma.sync.aligned.m16n8k8.row.col.f32.tf32.tf32.f32 "
        "{%0,%1,%2,%3}, {%4,%5,%6,%7}, {%8,%9}, {%0,%1,%2,%3};"
        : "+f"(c[0]), "+f"(c[1]), "+f"(c[2]), "+f"(c[3])
        : "r"(a[0]), "r"(a[1]), "r"(a[2]), "r"(a[3]),
          "r"(b[0]), "r"(b[1]));
}

__device__ __forceinline__ void mma_f16(float* c, const uint32_t* a, const uint32_t* b) {
    asm volatile(
        "mma.sync.aligned.m16n8k16.row.col.f32.f16.f16.f32 "
        "{%0,%1,%2,%3}, {%4,%5,%6,%7}, {%8,%9}, {%0,%1,%2,%3};"
        : "+f"(c[0]), "+f"(c[1]), "+f"(c[2]), "+f"(c[3])
        : "r"(a[0]), "r"(a[1]), "r"(a[2]), "r"(a[3]),
          "r"(b[0]), "r"(b[1]));
}

__device__ __forceinline__ void cp_async16(void* sptr, const void* gptr) {
    uint32_t sa = (uint32_t)__cvta_generic_to_shared(sptr);
    asm volatile("cp.async.cg.shared.global [%0], [%1], 16;\n" :: "r"(sa), "l"(gptr));
}
#define CP_COMMIT() asm volatile("cp.async.commit_group;\n" ::: "memory")
#define CP_WAIT0()  asm volatile("cp.async.wait_group 0;\n" ::: "memory")

// ---------------------------------------------------------------------------
// Fused transpose + fp16 convert of ALL weights, one launch.
// src: [K][N] f32 row-major.  dst: [N][Kp] half2 (uint32), kp = k/2.
// Thread per (layer, k-group of 8, n): 8 strided f32 reads (coalesced over n),
// one uint4 write (4 half2) at dst[n][kg*4 .. kg*4+3].
// ---------------------------------------------------------------------------
#define R0 110592
#define R1 221184
#define R2 331776
#define R3 442368
#define R4 884736                  // +w1: LL*(CC/8)*FF = 442368
#define R5 1327104                 // +w2: LL*(FF/8)*CC = 442368
#define R6 2863104                 // +lm: (CC/8)*VV    = 1536000

__global__ void cvt_trans_kernel(const float* __restrict__ wq, const float* __restrict__ wk,
                                 const float* __restrict__ wv, const float* __restrict__ wo,
                                 const float* __restrict__ w1, const float* __restrict__ w2,
                                 const float* __restrict__ lm, uint32_t* __restrict__ wt)
{
    int f = blockIdx.x * blockDim.x + threadIdx.x;
    if (f >= R6) return;
    const float* src; uint32_t* dst; int K, N, local;
    if (f < R0)      { src = wq; dst = wt + OFF16_WQ; K = CC; N = CC; local = f; }
    else if (f < R1) { src = wk; dst = wt + OFF16_WK; K = CC; N = CC; local = f - R0; }
    else if (f < R2) { src = wv; dst = wt + OFF16_WV; K = CC; N = CC; local = f - R1; }
    else if (f < R3) { src = wo; dst = wt + OFF16_WO; K = CC; N = CC; local = f - R2; }
    else if (f < R4) { src = w1; dst = wt + OFF16_W1; K = CC; N = FF; local = f - R3; }
    else if (f < R5) { src = w2; dst = wt + OFF16_W2; K = FF; N = CC; local = f - R4; }
    else             { src = lm; dst = wt + OFF16_LM; K = CC; N = VV; local = f - R5; }

    int Kp    = K >> 1;
    int PL    = (K >> 3) * N;          // groups per layer
    int layer = local / PL;
    int r     = local - layer * PL;
    int kg    = r / N;
    int n     = r - kg * N;

    const float* s0 = src + (size_t)layer*K*N + (size_t)(kg*8)*N + n;
    float s[8];
#pragma unroll
    for (int t = 0; t < 8; t++) s[t] = s0[(size_t)t*N];
    uint32_t* d = dst + (size_t)layer*N*Kp + (size_t)n*Kp + kg*4;
    uint4 o;
    o.x = packh2(s[0], s[1]);
    o.y = packh2(s[2], s[3]);
    o.z = packh2(s[4], s[5]);
    o.w = packh2(s[6], s[7]);
    *(uint4*)d = o;
}

// ---------------------------------------------------------------------------
// Embedding (f32 residual stream)
// ---------------------------------------------------------------------------
__global__ void embed_kernel(const int* __restrict__ idx,
                             const float* __restrict__ tok,
                             const float* __restrict__ pos,
                             float* __restrict__ X)
{
    int i = blockIdx.x * blockDim.x + threadIdx.x;
    if (i >= MM * (CC/4)) return;
    int row = i / (CC/4);
    int c4  = i % (CC/4);
    int t   = idx[row];
    int p   = row & (TT-1);
    float4 a = *(const float4*)(tok + (size_t)t*CC + c4*4);
    float4 e = *(const float4*)(pos + (size_t)p*CC + c4*4);
    a.x += e.x; a.y += e.y; a.z += e.z; a.w += e.w;
    *(float4*)(X + (size_t)row*CC + c4*4) = a;
}

// ---------------------------------------------------------------------------
// LayerNorm: one warp per row; output fp16 packed (half2 per uint32).
// Lane handles 6 column PAIRS: cols (64j + 2*lane, +1), j = 0..5.
// ---------------------------------------------------------------------------
__global__ void ln_kernel(const float* __restrict__ X,
                          const float* __restrict__ g,
                          const float* __restrict__ b,
                          uint32_t* __restrict__ Y)
{
    int row  = blockIdx.x * 8 + (threadIdx.x >> 5);
    int lane = threadIdx.x & 31;
    if (row >= MM) return;
    const float* x = X + (size_t)row*CC;
    float2 v[6];
    float s = 0.f, ss = 0.f;
#pragma unroll
    for (int j = 0; j < 6; j++) {
        int c = j*64 + 2*lane;
        v[j] = *(const float2*)(x + c);
        s  += v[j].x + v[j].y;
        ss += v[j].x*v[j].x + v[j].y*v[j].y;
    }
#pragma unroll
    for (int o = 16; o; o >>= 1) {
        s  += __shfl_xor_sync(0xFFFFFFFFu, s,  o);
        ss += __shfl_xor_sync(0xFFFFFFFFu, ss, o);
    }
    float mean = s  * (1.0f/CC);
    float var  = ss * (1.0f/CC) - mean*mean;
    float inv  = rsqrtf(var + 1e-5f);
    uint32_t* y = Y + (size_t)row*(CC/2);
#pragma unroll
    for (int j = 0; j < 6; j++) {
        int c = j*64 + 2*lane;
        float a0 = (v[j].x - mean)*inv*g[c    ] + b[c    ];
        float a1 = (v[j].y - mean)*inv*g[c + 1] + b[c + 1];
        y[j*32 + lane] = packh2(a0, a1);
    }
}

// ---------------------------------------------------------------------------
// FP16 GEMM: 128x128 tile, BK=32 (16 kp), 128 threads, warp tile 64x64,
// 2-stage cp.async. A [M][Kp] and B [N][Kp] both fp16-packed in gmem.
// m16n8k16: per k16-step 32 LDS.32 + 32 HMMA per warp.
// OUTMODE: 0 = f32, 1 = tf32 (for attention inputs), 2 = fp16 packed.
// ---------------------------------------------------------------------------
struct GemmSmemH {
    uint32_t As[2][128][20];   // 16 kp + pad4 (row 80B = 5x16)
    uint32_t Bs[2][128][20];
};
#define SMEM_GEMMH ((int)sizeof(GemmSmemH))   // 40960 bytes

template<bool RELU, bool RES, int OUTMODE>
__device__ __forceinline__
void gemm_core(GemmSmemH* sm,
               const uint32_t* __restrict__ A, const uint32_t* __restrict__ B,
               const float* __restrict__ bias, const float* __restrict__ res,
               void* __restrict__ Cv, int M, int N, int K, int bm, int bn)
{
    const int Kp   = K >> 1;
    const int tid  = threadIdx.x;
    const int lane = tid & 31;
    const int wid  = tid >> 5;
    const int wm = (wid & 1) * 64;
    const int wn = (wid >> 1) * 64;
    const int grp = lane >> 2;
    const int tg  = lane & 3;

    float acc[4][8][4];
#pragma unroll
    for (int mt = 0; mt < 4; mt++)
#pragma unroll
        for (int nt = 0; nt < 8; nt++)
#pragma unroll
            for (int e = 0; e < 4; e++) acc[mt][nt][e] = 0.f;

    auto issue = [&](int s, int k0p) {
#pragma unroll
        for (int p = 0; p < 4; p++) {          // A: 128 rows x 16 uints = 512 chunks
            int i  = tid + p*128;
            int r  = i >> 2;
            int c4 = (i & 3) * 4;
            cp_async16(&sm->As[s][r][c4], A + (size_t)(bm + r)*Kp + k0p + c4);
        }
#pragma unroll
        for (int p = 0; p < 4; p++) {          // B: 128 n x 16 uints
            int i  = tid + p*128;
            int r  = i >> 2;
            int c4 = (i & 3) * 4;
            cp_async16(&sm->Bs[s][r][c4], B + (size_t)(bn + r)*Kp + k0p + c4);
        }
        CP_COMMIT();
    };

    const int nIter = K >> 5;
    issue(0, 0);

    for (int it = 0; it < nIter; it++) {
        const int cur = it & 1;
        CP_WAIT0();
        __syncthreads();
        if (it + 1 < nIter) issue(cur ^ 1, (it + 1) << 4);

#pragma unroll
        for (int kps = 0; kps < 16; kps += 8) {
            uint32_t af[4][4], bf[8][2];
#pragma unroll
            for (int mt = 0; mt < 4; mt++) {
                int r = wm + mt*16 + grp;
                af[mt][0] = sm->As[cur][r    ][kps + tg    ];
                af[mt][1] = sm->As[cur][r + 8][kps + tg    ];
                af[mt][2] = sm->As[cur][r    ][kps + tg + 4];
                af[mt][3] = sm->As[cur][r + 8][kps + tg + 4];
            }
#pragma unroll
            for (int nt = 0; nt < 8; nt++) {
                int c = wn + nt*8 + grp;
                bf[nt][0] = sm->Bs[cur][c][kps + tg    ];
                bf[nt][1] = sm->Bs[cur][c][kps + tg + 4];
            }
#pragma unroll
            for (int mt = 0; mt < 4; mt++)
#pragma unroll
                for (int nt = 0; nt < 8; nt++)
                    mma_f16(acc[mt][nt], af[mt], bf[nt]);
        }
    }

    // Epilogue
#pragma unroll
    for (int mt = 0; mt < 4; mt++) {
        int r0 = bm + wm + mt*16 + grp;
        int r1 = r0 + 8;
#pragma unroll
        for (int nt = 0; nt < 8; nt++) {
            int c = bn + wn + nt*8 + tg*2;
            float o0x = acc[mt][nt][0], o0y = acc[mt][nt][1];
            float o1x = acc[mt][nt][2], o1y = acc[mt][nt][3];
            if (bias) {
                float bv0 = bias[c], bv1 = bias[c+1];
                o0x += bv0; o0y += bv1; o1x += bv0; o1y += bv1;
            }
            if (RES) {
                float2 ra = *(const float2*)(res + (size_t)r0*N + c);
                float2 rb = *(const float2*)(res + (size_t)r1*N + c);
                o0x += ra.x; o0y += ra.y; o1x += rb.x; o1y += rb.y;
            }
            if (RELU) {
                o0x = fmaxf(o0x, 0.f); o0y = fmaxf(o0y, 0.f);
                o1x = fmaxf(o1x, 0.f); o1y = fmaxf(o1y, 0.f);
            }
            if (OUTMODE == 0) {
                float* C = (float*)Cv;
                float2 w0 = {o0x, o0y};
                float2 w1 = {o1x, o1y};
                *(float2*)(C + (size_t)r0*N + c) = w0;
                *(float2*)(C + (size_t)r1*N + c) = w1;
            } else if (OUTMODE == 1) {
                uint32_t* C = (uint32_t*)Cv;
                uint2 w0 = {f2tf(o0x), f2tf(o0y)};
                uint2 w1 = {f2tf(o1x), f2tf(o1y)};
                *(uint2*)(C + (size_t)r0*N + c) = w0;
                *(uint2*)(C + (size_t)r1*N + c) = w1;
            } else {
                uint32_t* C = (uint32_t*)Cv;
                C[(size_t)r0*(N>>1) + (c>>1)] = packh2(o0x, o0y);
                C[(size_t)r1*(N>>1) + (c>>1)] = packh2(o1x, o1y);
            }
        }
    }
}

template<bool RELU, bool RES, int OUTMODE>
__global__ __launch_bounds__(128)
void tgemm(const uint32_t* __restrict__ A, const uint32_t* __restrict__ B,
           const float* __restrict__ bias, const float* __restrict__ res,
           void* __restrict__ C, int M, int N, int K)
{
    extern __shared__ GemmSmemH smg[];
    gemm_core<RELU, RES, OUTMODE>(smg, A, B, bias, res, C, M, N, K,
                                  blockIdx.y * 128, blockIdx.x * 128);
}

// Fused QKV: grid.x = 9 (3 matrices x 3 col-tiles), grid.y = 64. tf32 out.
__global__ __launch_bounds__(128)
void qkv_gemm(const uint32_t* __restrict__ A,
              const uint32_t* __restrict__ Wq, const uint32_t* __restrict__ Wk,
              const uint32_t* __restrict__ Wv,
              uint32_t* __restrict__ Q, uint32_t* __restrict__ Ko, uint32_t* __restrict__ V)
{
    extern __shared__ GemmSmemH smg[];
    int sel = blockIdx.x / 3;
    int bn  = (blockIdx.x % 3) * 128;
    const uint32_t* B = (sel == 0) ? Wq : (sel == 1) ? Wk : Wv;
    uint32_t*       C = (sel == 0) ? Q  : (sel == 1) ? Ko : V;
    gemm_core<false, false, 1>(smg, A, B, nullptr, nullptr, C,
                               MM, CC, CC, blockIdx.y * 128, bn);
}

// ---------------------------------------------------------------------------
// Small-M-tile FP16 GEMM for N=384 projections (Wo, W2): 64x128 tile,
// 4 warps of 32x64, 2-stage cp.async, 4 CTAs/SM. bias+residual, f32 out.
// ---------------------------------------------------------------------------
struct GemmSmemH64 {
    uint32_t As[2][64][20];    // 10240 B
    uint32_t Bs[2][128][20];   // 20480 B
};
#define SMEM_GEMMH64 ((int)sizeof(GemmSmemH64))   // 30720 bytes

__global__ __launch_bounds__(128, 4)
void tgemm64(const uint32_t* __restrict__ A, const uint32_t* __restrict__ B,
             const float* __restrict__ bias, const float* __restrict__ res,
             float* __restrict__ C, int M, int N, int K)
{
    extern __shared__ GemmSmemH64 sm64[];
    GemmSmemH64* sm = sm64;

    const int Kp   = K >> 1;
    const int bm = blockIdx.y * 64;
    const int bn = blockIdx.x * 128;
    const int tid  = threadIdx.x;
    const int lane = tid & 31;
    const int wid  = tid >> 5;
    const int wm = (wid & 1) * 32;
    const int wn = (wid >> 1) * 64;
    const int grp = lane >> 2;
    const int tg  = lane & 3;

    float acc[2][8][4];
#pragma unroll
    for (int mt = 0; mt < 2; mt++)
#pragma unroll
        for (int nt = 0; nt < 8; nt++)
#pragma unroll
            for (int e = 0; e < 4; e++) acc[mt][nt][e] = 0.f;

    auto issue = [&](int s, int k0p) {
#pragma unroll
        for (int p = 0; p < 2; p++) {          // A: 64 rows x 16 uints = 256 chunks
            int i  = tid + p*128;
            int r  = i >> 2;
            int c4 = (i & 3) * 4;
            cp_async16(&sm->As[s][r][c4], A + (size_t)(bm + r)*Kp + k0p + c4);
        }
#pragma unroll
        for (int p = 0; p < 4; p++) {          // B: 128 n x 16 uints = 512 chunks
            int i  = tid + p*128;
            int r  = i >> 2;
            int c4 = (i & 3) * 4;
            cp_async16(&sm->Bs[s][r][c4], B + (size_t)(bn + r)*Kp + k0p + c4);
        }
        CP_COMMIT();
    };

    const int nIter = K >> 5;
    issue(0, 0);

    for (int it = 0; it < nIter; it++) {
        const int cur = it & 1;
        CP_WAIT0();
        __syncthreads();
        if (it + 1 < nIter) issue(cur ^ 1, (it + 1) << 4);

#pragma unroll
        for (int kps = 0; kps < 16; kps += 8) {
            uint32_t af[2][4], bf[8][2];
#pragma unroll
            for (int mt = 0; mt < 2; mt++) {
                int r = wm + mt*16 + grp;
                af[mt][0] = sm->As[cur][r    ][kps + tg    ];
                af[mt][1] = sm->As[cur][r + 8][kps + tg    ];
                af[mt][2] = sm->As[cur][r    ][kps + tg + 4];
                af[mt][3] = sm->As[cur][r + 8][kps + tg + 4];
            }
#pragma unroll
            for (int nt = 0; nt < 8; nt++) {
                int c = wn + nt*8 + grp;
                bf[nt][0] = sm->Bs[cur][c][kps + tg    ];
                bf[nt][1] = sm->Bs[cur][c][kps + tg + 4];
            }
#pragma unroll
            for (int mt = 0; mt < 2; mt++)
#pragma unroll
                for (int nt = 0; nt < 8; nt++)
                    mma_f16(acc[mt][nt], af[mt], bf[nt]);
        }
    }

#pragma unroll
    for (int mt = 0; mt < 2; mt++) {
        int r0 = bm + wm + mt*16 + grp;
        int r1 = r0 + 8;
#pragma unroll
        for (int nt = 0; nt < 8; nt++) {
            int c = bn + wn + nt*8 + tg*2;
            float bv0 = bias[c], bv1 = bias[c+1];
            float2 ra = *(const float2*)(res + (size_t)r0*N + c);
            float2 rb = *(const float2*)(res + (size_t)r1*N + c);
            float2 w0 = {acc[mt][nt][0] + bv0 + ra.x, acc[mt][nt][1] + bv1 + ra.y};
            float2 w1 = {acc[mt][nt][2] + bv0 + rb.x, acc[mt][nt][3] + bv1 + rb.y};
            *(float2*)(C + (size_t)r0*N + c) = w0;
            *(float2*)(C + (size_t)r1*N + c) = w1;
        }
    }
}

// ---------------------------------------------------------------------------
// Tensor-core flash attention; q/k/v tf32 (unchanged math), att output fp16.
// ---------------------------------------------------------------------------
#define AKS 68
#define AVS 72
#define APS 36
#define ATT_SMEM ((TT*AKS + TT*AVS + 8*32*APS) * (int)sizeof(uint32_t))

__global__ __launch_bounds__(256, 1)
void attn_mma(const uint32_t* __restrict__ Q, const uint32_t* __restrict__ K,
              const uint32_t* __restrict__ V, uint32_t* __restrict__ O)
{
    extern __shared__ uint32_t sm[];
    uint32_t* Ks = sm;
    uint32_t* Vs = sm + TT*AKS;
    uint32_t* Pb = sm + TT*AKS + TT*AVS;

    const int bh = blockIdx.x;
    const int b  = bh / NH;
    const int h  = bh % NH;
    const float scale = 0.05103103630798288f;  // 1/sqrt(384)

    const int tid = threadIdx.x;
    const uint32_t* kbase = K + (size_t)b*TT*CC + h*HD;
    const uint32_t* vbase = V + (size_t)b*TT*CC + h*HD;

    for (int i = tid; i < TT*16; i += 256) {
        int t  = i >> 4;
        int d4 = (i & 15) * 4;
        *(uint4*)&Ks[t*AKS + d4] = *(const uint4*)(kbase + (size_t)t*CC + d4);
        *(uint4*)&Vs[t*AVS + d4] = *(const uint4*)(vbase + (size_t)t*CC + d4);
    }
    __syncthreads();

    const int lane = tid & 31;
    const int w    = tid >> 5;
    const int grp  = lane >> 2;
    const int tg   = lane & 3;
    const int q0   = w * 32;

    const uint32_t* qbase = Q + (size_t)b*TT*CC + h*HD;
    uint32_t qa[2][8][4];
#pragma unroll
    for (int mt = 0; mt < 2; mt++) {
        int ra = q0 + mt*16 + grp;
        int rb = ra + 8;
#pragma unroll
        for (int ks = 0; ks < 8; ks++) {
            int d = ks*8 + tg;
            qa[mt][ks][0] = qbase[(size_t)ra*CC + d    ];
            qa[mt][ks][1] = qbase[(size_t)rb*CC + d    ];
            qa[mt][ks][2] = qbase[(size_t)ra*CC + d + 4];
            qa[mt][ks][3] = qbase[(size_t)rb*CC + d + 4];
        }
    }

    float o[2][8][4];
#pragma unroll
    for (int mt = 0; mt < 2; mt++)
#pragma unroll
        for (int nt = 0; nt < 8; nt++)
#pragma unroll
            for (int e = 0; e < 4; e++) o[mt][nt][e] = 0.f;

    float mrow[2][2] = {{-1e30f,-1e30f},{-1e30f,-1e30f}};
    float lrow[2][2] = {{0.f,0.f},{0.f,0.f}};

    uint32_t* myP = Pb + w * 32 * APS;

    for (int j = 0; j <= w; j++) {
        const int kbeg = j * 32;
        float s[2][4][4];
#pragma unroll
        for (int mt = 0; mt < 2; mt++)
#pragma unroll
            for (int nt = 0; nt < 4; nt++)
#pragma unroll
                for (int e = 0; e < 4; e++) s[mt][nt][e] = 0.f;

#pragma unroll
        for (int ks = 0; ks < 8; ks++) {
            uint32_t bf[4][2];
#pragma unroll
            for (int nt = 0; nt < 4; nt++) {
                int key = kbeg + nt*8 + grp;
                int d   = ks*8 + tg;
                bf[nt][0] = Ks[key*AKS + d    ];
                bf[nt][1] = Ks[key*AKS + d + 4];
            }
#pragma unroll
            for (int mt = 0; mt < 2; mt++)
#pragma unroll
                for (int nt = 0; nt < 4; nt++)
                    mma_tf32(s[mt][nt], qa[mt][ks], bf[nt]);
        }

#pragma unroll
        for (int mt = 0; mt < 2; mt++) {
            int ra = q0 + mt*16 + grp;
            int rb = ra + 8;
            float rmax0 = -1e30f, rmax1 = -1e30f;
#pragma unroll
            for (int nt = 0; nt < 4; nt++) {
                int c0 = kbeg + nt*8 + 2*tg;
#pragma unroll
                for (int e = 0; e < 4; e++) {
                    float vv = s[mt][nt][e] * scale;
                    int col = c0 + (e & 1);
                    int row = (e < 2) ? ra : rb;
                    if (j == w && col > row) vv = -1e30f;
                    s[mt][nt][e] = vv;
                }
                rmax0 = fmaxf(rmax0, fmaxf(s[mt][nt][0], s[mt][nt][1]));
                rmax1 = fmaxf(rmax1, fmaxf(s[mt][nt][2], s[mt][nt][3]));
            }
            rmax0 = fmaxf(rmax0, __shfl_xor_sync(0xFFFFFFFFu, rmax0, 1));
            rmax0 = fmaxf(rmax0, __shfl_xor_sync(0xFFFFFFFFu, rmax0, 2));
            rmax1 = fmaxf(rmax1, __shfl_xor_sync(0xFFFFFFFFu, rmax1, 1));
            rmax1 = fmaxf(rmax1, __shfl_xor_sync(0xFFFFFFFFu, rmax1, 2));

            float mn0 = fmaxf(mrow[mt][0], rmax0);
            float mn1 = fmaxf(mrow[mt][1], rmax1);
            float cr0 = __expf(mrow[mt][0] - mn0);
            float cr1 = __expf(mrow[mt][1] - mn1);
            mrow[mt][0] = mn0; mrow[mt][1] = mn1;

            float rs0 = 0.f, rs1 = 0.f;
#pragma unroll
            for (int nt = 0; nt < 4; nt++) {
                float p0 = __expf(s[mt][nt][0] - mn0);
                float p1 = __expf(s[mt][nt][1] - mn0);
                float p2 = __expf(s[mt][nt][2] - mn1);
                float p3 = __expf(s[mt][nt][3] - mn1);
                rs0 += p0 + p1; rs1 += p2 + p3;
                int cb = nt*8 + 2*tg;
                myP[(mt*16 + grp    )*APS + cb    ] = f2tf(p0);
                myP[(mt*16 + grp    )*APS + cb + 1] = f2tf(p1);
                myP[(mt*16 + grp + 8)*APS + cb    ] = f2tf(p2);
                myP[(mt*16 + grp + 8)*APS + cb + 1] = f2tf(p3);
            }
            rs0 += __shfl_xor_sync(0xFFFFFFFFu, rs0, 1);
            rs0 += __shfl_xor_sync(0xFFFFFFFFu, rs0, 2);
            rs1 += __shfl_xor_sync(0xFFFFFFFFu, rs1, 1);
            rs1 += __shfl_xor_sync(0xFFFFFFFFu, rs1, 2);
            lrow[mt][0] = lrow[mt][0]*cr0 + rs0;
            lrow[mt][1] = lrow[mt][1]*cr1 + rs1;
#pragma unroll
            for (int nt = 0; nt < 8; nt++) {
                o[mt][nt][0] *= cr0; o[mt][nt][1] *= cr0;
                o[mt][nt][2] *= cr1; o[mt][nt][3] *= cr1;
            }
        }
        __syncwarp();

#pragma unroll
        for (int ks2 = 0; ks2 < 4; ks2++) {
            uint32_t vb[8][2];
#pragma unroll
            for (int nt = 0; nt < 8; nt++) {
                int key = kbeg + ks2*8 + tg;
                int d   = nt*8 + grp;
                vb[nt][0] = Vs[ key     *AVS + d];
                vb[nt][1] = Vs[(key + 4)*AVS + d];
            }
#pragma unroll
            for (int mt = 0; mt < 2; mt++) {
                uint32_t pa[4];
                pa[0] = myP[(mt*16 + grp    )*APS + ks2*8 + tg    ];
                pa[1] = myP[(mt*16 + grp + 8)*APS + ks2*8 + tg    ];
                pa[2] = myP[(mt*16 + grp    )*APS + ks2*8 + tg + 4];
                pa[3] = myP[(mt*16 + grp + 8)*APS + ks2*8 + tg + 4];
#pragma unroll
                for (int nt = 0; nt < 8; nt++)
                    mma_tf32(o[mt][nt], pa, vb[nt]);
            }
        }
        __syncwarp();
    }

    // Epilogue: att output fp16 packed [row][kp], Kp = CC/2 = 192.
    uint32_t* obase = O + (size_t)b*TT*(CC/2) + h*(HD/2);
#pragma unroll
    for (int mt = 0; mt < 2; mt++) {
        int ra = q0 + mt*16 + grp;
        int rb = ra + 8;
        float inv0 = 1.f / lrow[mt][0];
        float inv1 = 1.f / lrow[mt][1];
#pragma unroll
        for (int nt = 0; nt < 8; nt++) {
            int dp = nt*4 + tg;   // (nt*8 + 2*tg)/2
            obase[(size_t)ra*(CC/2) + dp] = packh2(o[mt][nt][0]*inv0, o[mt][nt][1]*inv0);
            obase[(size_t)rb*(CC/2) + dp] = packh2(o[mt][nt][2]*inv1, o[mt][nt][3]*inv1);
        }
    }
}

// ---------------------------------------------------------------------------
// Host
// ---------------------------------------------------------------------------
extern "C" void kernel_launch(void* const* d_in, const int* in_sizes, int n_in,
                              void* d_out, int out_size)
{
    (void)in_sizes; (void)n_in; (void)out_size;

    const int*   idx     = (const int*)  d_in[0];
    const float* tok_emb = (const float*)d_in[1];
    const float* pos_emb = (const float*)d_in[2];
    const float* ln1_g   = (const float*)d_in[3];
    const float* ln1_b   = (const float*)d_in[4];
    const float* wq      = (const float*)d_in[5];
    const float* wk      = (const float*)d_in[6];
    const float* wv      = (const float*)d_in[7];
    const float* wo      = (const float*)d_in[8];
    const float* wo_b    = (const float*)d_in[9];
    const float* ln2_g   = (const float*)d_in[10];
    const float* ln2_b   = (const float*)d_in[11];
    const float* w1      = (const float*)d_in[12];
    const float* b1      = (const float*)d_in[13];
    const float* w2      = (const float*)d_in[14];
    const float* b2      = (const float*)d_in[15];
    const float* lnf_g   = (const float*)d_in[16];
    const float* lnf_b   = (const float*)d_in[17];
    const float* lm_w    = (const float*)d_in[18];
    const float* lm_b    = (const float*)d_in[19];
    float* out = (float*)d_out;

    float *x;
    uint32_t *h, *q, *k, *v, *att, *u, *wt;
    cudaGetSymbolAddress((void**)&x,   g_x);
    cudaGetSymbolAddress((void**)&h,   g_h);
    cudaGetSymbolAddress((void**)&q,   g_q);
    cudaGetSymbolAddress((void**)&k,   g_k);
    cudaGetSymbolAddress((void**)&v,   g_v);
    cudaGetSymbolAddress((void**)&att, g_att);
    cudaGetSymbolAddress((void**)&u,   g_u);
    cudaGetSymbolAddress((void**)&wt,  g_wt);

    cudaFuncSetAttribute(attn_mma, cudaFuncAttributeMaxDynamicSharedMemorySize, ATT_SMEM);
    cudaFuncSetAttribute(tgemm<false,false,0>, cudaFuncAttributeMaxDynamicSharedMemorySize, SMEM_GEMMH);
    cudaFuncSetAttribute(tgemm<true ,false,2>, cudaFuncAttributeMaxDynamicSharedMemorySize, SMEM_GEMMH);
    cudaFuncSetAttribute(qkv_gemm,             cudaFuncAttributeMaxDynamicSharedMemorySize, SMEM_GEMMH);
    cudaFuncSetAttribute(tgemm64,              cudaFuncAttributeMaxDynamicSharedMemorySize, SMEM_GEMMH64);

    // Pre-convert + transpose all weights to fp16 [N][Kp] (single launch)
    cvt_trans_kernel<<<(R6 + 255)/256, 256>>>(wq, wk, wv, wo, w1, w2, lm_w, wt);

    {
        int total = MM * (CC/4);
        embed_kernel<<<(total + 255)/256, 256>>>(idx, tok_emb, pos_emb, x);
    }

    for (int L = 0; L < LL; L++) {
        const float* g1  = ln1_g + (size_t)L*CC;
        const float* bg1 = ln1_b + (size_t)L*CC;
        const uint32_t* Wq = wt + OFF16_WQ + (size_t)L*(CC*CC/2);
        const uint32_t* Wk = wt + OFF16_WK + (size_t)L*(CC*CC/2);
        const uint32_t* Wv = wt + OFF16_WV + (size_t)L*(CC*CC/2);
        const uint32_t* Wo = wt + OFF16_WO + (size_t)L*(CC*CC/2);
        const float* Wob = wo_b + (size_t)L*CC;
        const float* g2  = ln2_g + (size_t)L*CC;
        const float* bg2 = ln2_b + (size_t)L*CC;
        const uint32_t* W1 = wt + OFF16_W1 + (size_t)L*(CC*FF/2);
        const float* B1  = b1 + (size_t)L*FF;
        const uint32_t* W2 = wt + OFF16_W2 + (size_t)L*(FF*CC/2);
        const float* B2  = b2 + (size_t)L*CC;

        ln_kernel<<<MM/8, 256>>>(x, g1, bg1, h);
        qkv_gemm<<<dim3(9, 64), 128, SMEM_GEMMH>>>(h, Wq, Wk, Wv, q, k, v);
        attn_mma<<<BB*NH, 256, ATT_SMEM>>>(q, k, v, att);
        // x += att @ Wo + wo_b
        tgemm64<<<dim3(CC/128, MM/64), 128, SMEM_GEMMH64>>>(
            att, Wo, Wob, x, x, MM, CC, CC);
        ln_kernel<<<MM/8, 256>>>(x, g2, bg2, h);
        // u = relu(h @ W1 + b1), fp16 out
        tgemm<true,false,2><<<dim3(FF/128, MM/128), 128, SMEM_GEMMH>>>(
            h, W1, B1, nullptr, u, MM, FF, CC);
        // x += u @ W2 + b2
        tgemm64<<<dim3(CC/128, MM/64), 128, SMEM_GEMMH64>>>(
            u, W2, B2, x, x, MM, CC, FF);
    }

    ln_kernel<<<MM/8, 256>>>(x, lnf_g, lnf_b, h);
    // logits = h @ lm_w + lm_b
    tgemm<false,false,0><<<dim3(VV/128, MM/128), 128, SMEM_GEMMH>>>(
        h, wt + OFF16_LM, lm_b, nullptr, out, MM, VV, CC);
}